// round 14
// baseline (speedup 1.0000x reference)
#include <cuda_runtime.h>
#include <cuda_bf16.h>
#include <math.h>
#include <stdint.h>

#define DMQ 512
#define DIQ 1024
#define DSQ 16
#define DCQ 4
#define DTRQ 32
#define NLQ 2
#define NTOK 4096
#define F0Q 1024
#define KSPLIT 8

typedef __nv_bfloat16 bf16;
typedef __nv_bfloat162 bf162;

// ---------------- scratch (device globals: allocation-free) ----------------
__device__ float g_h[NTOK * DMQ];
__device__ float g_ln[NTOK * DMQ];
__device__ float g_dbc[NTOK * 64];
__device__ float g_dbcp[KSPLIT * NTOK * 64];
__device__ float g_Aend[64 * DIQ * DSQ];
__device__ float g_Hend[64 * DIQ * DSQ];
__device__ float g_Hstart[64 * DIQ * DSQ];
__device__ float g_attnk[NTOK * 128];
__device__ float g_asc[NTOK];
__device__ float g_wts[NTOK];
__device__ float g_pooled[DMQ];
// bf16 buffers
__device__ bf16 g_x16[NTOK * F0Q];
__device__ bf16 g_ln16[NTOK * DMQ];
__device__ bf16 g_xz16[NTOK * 2 * DIQ];
__device__ bf16 g_xs16[NTOK * DIQ];
__device__ bf16 g_delta16[NTOK * DIQ];
__device__ bf16 g_y16[NTOK * DIQ];
__device__ bf16 g_fc1w16[DMQ * F0Q];
__device__ bf16 g_ipw16[NLQ * 2 * DIQ * DMQ];
__device__ bf16 g_xpw16[NLQ * 64 * DIQ];
__device__ bf16 g_opw16[NLQ * DMQ * DIQ];
__device__ bf16 g_aw116[128 * DMQ];

// ---------------- PTX helpers ------------------------------------------------
__device__ __forceinline__ uint32_t smem_u32(const void* p) {
    uint32_t a;
    asm("{ .reg .u64 t; cvta.to.shared.u64 t, %1; cvt.u32.u64 %0, t; }"
        : "=r"(a) : "l"(p));
    return a;
}

__device__ __forceinline__ void cp_async16(uint32_t dst, const void* src) {
    asm volatile("cp.async.ca.shared.global [%0], [%1], 16;"
                 :: "r"(dst), "l"(src) : "memory");
}
__device__ __forceinline__ void cp_commit() {
    asm volatile("cp.async.commit_group;" ::: "memory");
}
template <int N>
__device__ __forceinline__ void cp_wait() {
    asm volatile("cp.async.wait_group %0;" :: "n"(N) : "memory");
}

__device__ __forceinline__ void ldsm4(uint32_t* r, uint32_t addr) {
    asm volatile("ldmatrix.sync.aligned.m8n8.x4.shared.b16 {%0,%1,%2,%3}, [%4];"
                 : "=r"(r[0]), "=r"(r[1]), "=r"(r[2]), "=r"(r[3]) : "r"(addr));
}

__device__ __forceinline__ void mma_bf16(float* d, const uint32_t* a, const uint32_t* b) {
    asm volatile(
        "mma.sync.aligned.m16n8k16.row.col.f32.bf16.bf16.f32 "
        "{%0,%1,%2,%3}, {%4,%5,%6,%7}, {%8,%9}, {%0,%1,%2,%3};\n"
        : "+f"(d[0]), "+f"(d[1]), "+f"(d[2]), "+f"(d[3])
        : "r"(a[0]), "r"(a[1]), "r"(a[2]), "r"(a[3]), "r"(b[0]), "r"(b[1]));
}

// ---------------- fp32 -> bf16 convert (up to 3 regions per launch) ----------
__global__ void cvt3_kernel(const float* __restrict__ s0, bf16* __restrict__ d0, int n0,
                            const float* __restrict__ s1, bf16* __restrict__ d1, int n1,
                            const float* __restrict__ s2, bf16* __restrict__ d2, int n2)
{
    int i = blockIdx.x * blockDim.x + threadIdx.x;
    const float* s; bf16* d; int j;
    if (i < n0)               { s = s0; d = d0; j = i; }
    else if (i < n0 + n1)     { s = s1; d = d1; j = i - n0; }
    else if (i < n0 + n1 + n2){ s = s2; d = d2; j = i - n0 - n1; }
    else return;
    const float4 v = ((const float4*)s)[j];
    bf162* o = (bf162*)d;
    o[2 * j]     = __floats2bfloat162_rn(v.x, v.y);
    o[2 * j + 1] = __floats2bfloat162_rn(v.z, v.w);
}

// ---------------- bf16 tensor-core GEMM -------------------------------------
// C = A[M,K] * B[N,K]^T, bf16 row-major. CTA 128 x NT, 256 thr / 8 warps.
// BK=32, STAGES-deep cp.async ring. Rows padded to 80 B.
// EPI: 0 none, 1 bias+relu, 3 residual add, 4 bias+tanh
// SPLITK: grid.z = K-slice; fp32 partials at C + z*ldaux.
#define RSB 80

template <int EPI, int NT, int STAGES, bool WB16, bool WF32, bool SPLITK>
__global__ __launch_bounds__(256, (STAGES > 4 ? 1 : 2)) void gemm16_kernel(
    const bf16* __restrict__ A, int lda,
    const bf16* __restrict__ B, int ldb,
    float* __restrict__ C, int ldc,
    bf16* __restrict__ C16,
    const float* __restrict__ aux, int ldaux,
    int K)
{
    constexpr int WN = NT / 32;
    constexpr int WM = 8 / WN;
    constexpr int MI = 128 / (WM * 16);
    constexpr int NI = 4;
    constexpr int ASTG = 128 * RSB;
    constexpr int BSTG = NT * RSB;
    constexpr int STGB = ASTG + BSTG;

    extern __shared__ char smraw[];
    const uint32_t sbase = smem_u32(smraw);

    const int tid = threadIdx.x;
    const int wid = tid >> 5;
    const int lane = tid & 31;
    const int fr = lane >> 2;
    const int fc = lane & 3;
    const int wm = (wid % WM) * (MI * 16);
    const int wn = (wid / WM) * 32;
    const int bm = blockIdx.y * 128;
    const int bn = blockIdx.x * NT;

    if (SPLITK) {
        A += (size_t)blockIdx.z * K;
        B += (size_t)blockIdx.z * K;
    }

    float acc[MI][NI][4];
#pragma unroll
    for (int mi = 0; mi < MI; mi++)
#pragma unroll
        for (int ni = 0; ni < NI; ni++)
#pragma unroll
            for (int j = 0; j < 4; j++) acc[mi][ni][j] = 0.f;

    auto load_stage = [&](int stg, int c) {
        const int k0 = c << 5;
        const uint32_t abuf = sbase + stg * STGB;
        const uint32_t bbuf = abuf + ASTG;
#pragma unroll
        for (int i = 0; i < 2; i++) {
            const int u = tid + i * 256;
            const int r = u >> 2, q = u & 3;
            cp_async16(abuf + r * RSB + q * 16,
                       A + (size_t)(bm + r) * lda + k0 + q * 8);
        }
#pragma unroll
        for (int i = 0; i < NT / 64; i++) {
            const int u = tid + i * 256;
            const int r = u >> 2, q = u & 3;
            cp_async16(bbuf + r * RSB + q * 16,
                       B + (size_t)(bn + r) * ldb + k0 + q * 8);
        }
    };

    const int nch = K >> 5;
#pragma unroll
    for (int i = 0; i < STAGES - 1; i++) {
        if (i < nch) load_stage(i, i);
        cp_commit();
    }

    const int a_r = lane & 15, a_c8 = (lane >> 4) << 3;
    const int b_r = (lane & 7) + ((lane >> 4) << 3), b_c8 = lane & 8;

    for (int c = 0; c < nch; c++) {
        const int stg = c % STAGES;
        cp_wait<STAGES - 2>();
        __syncthreads();

        if (c + STAGES - 1 < nch) load_stage((c + STAGES - 1) % STAGES, c + STAGES - 1);
        cp_commit();

        const uint32_t abuf = sbase + stg * STGB;
        const uint32_t bbuf = abuf + ASTG;
#pragma unroll
        for (int kk = 0; kk < 2; kk++) {
            const int kb = kk << 4;
            uint32_t afr[MI][4], bfr[NI][2];
#pragma unroll
            for (int mi = 0; mi < MI; mi++)
                ldsm4(afr[mi],
                      abuf + (wm + mi * 16 + a_r) * RSB + (kb + a_c8) * 2);
#pragma unroll
            for (int n2 = 0; n2 < NI / 2; n2++) {
                uint32_t r4[4];
                ldsm4(r4, bbuf + (wn + n2 * 16 + b_r) * RSB + (kb + b_c8) * 2);
                bfr[2 * n2][0] = r4[0]; bfr[2 * n2][1] = r4[1];
                bfr[2 * n2 + 1][0] = r4[2]; bfr[2 * n2 + 1][1] = r4[3];
            }
#pragma unroll
            for (int mi = 0; mi < MI; mi++)
#pragma unroll
                for (int ni = 0; ni < NI; ni++)
                    mma_bf16(acc[mi][ni], afr[mi], bfr[ni]);
        }
    }

    float* Cw = C;
    if (SPLITK) Cw = C + (size_t)blockIdx.z * ldaux;

#pragma unroll
    for (int mi = 0; mi < MI; mi++) {
#pragma unroll
        for (int ni = 0; ni < NI; ni++) {
#pragma unroll
            for (int half = 0; half < 2; half++) {
                const int m = bm + wm + mi * 16 + fr + (half << 3);
                const int n = bn + wn + ni * 8 + (fc << 1);
                float v0 = acc[mi][ni][half * 2 + 0];
                float v1 = acc[mi][ni][half * 2 + 1];
                if (EPI == 1) {
                    v0 = fmaxf(v0 + aux[n], 0.f);
                    v1 = fmaxf(v1 + aux[n + 1], 0.f);
                } else if (EPI == 3) {
                    const float2 r = *(const float2*)(aux + (size_t)m * ldaux + n);
                    v0 += r.x; v1 += r.y;
                } else if (EPI == 4) {
                    v0 = tanhf(v0 + aux[n]);
                    v1 = tanhf(v1 + aux[n + 1]);
                }
                if (SPLITK || WF32) {
                    float2 o; o.x = v0; o.y = v1;
                    *(float2*)(Cw + (size_t)m * ldc + n) = o;
                }
                if (!SPLITK && WB16)
                    *(bf162*)(C16 + (size_t)m * ldc + n) = __floats2bfloat162_rn(v0, v1);
            }
        }
    }
}

// ---------------- split-K reduce for dbc ------------------------------------
__global__ void dbc_reduce_kernel(const float* __restrict__ part,
                                  float* __restrict__ dbc)
{
    const int i = blockIdx.x * blockDim.x + threadIdx.x;
    float4 s = ((const float4*)part)[i];
#pragma unroll
    for (int k = 1; k < KSPLIT; k++) {
        const float4 v = ((const float4*)(part + (size_t)k * NTOK * 64))[i];
        s.x += v.x; s.y += v.y; s.z += v.z; s.w += v.w;
    }
    ((float4*)dbc)[i] = s;
}

// ---------------- delta: softplus(dbc[:,:32] @ dtw^T + dtb) ------------------
// block: 256 threads = 256 d-channels, 64 tokens; dtw row in 32 registers.
// grid: (DIQ/256, NTOK/64)
__global__ __launch_bounds__(256) void delta_kernel(
    const float* __restrict__ dbc,
    const float* __restrict__ dtw,
    const float* __restrict__ dtb,
    bf16* __restrict__ delta16)
{
    const int d = blockIdx.x * 256 + threadIdx.x;
    const int n0 = blockIdx.y * 64;

    __shared__ float sh_dt[64][32];
    for (int i = threadIdx.x; i < 64 * 32; i += 256)
        sh_dt[i >> 5][i & 31] = dbc[(size_t)(n0 + (i >> 5)) * 64 + (i & 31)];

    float w[32];
#pragma unroll
    for (int k = 0; k < 32; k++) w[k] = dtw[(size_t)d * DTRQ + k];
    const float bias = dtb[d];
    __syncthreads();

#pragma unroll 4
    for (int n = 0; n < 64; n++) {
        float a = bias;
#pragma unroll
        for (int k = 0; k < 32; k++) a += sh_dt[n][k] * w[k];
        a = (a > 20.f) ? a : log1pf(expf(a));
        delta16[(size_t)(n0 + n) * DIQ + d] = __float2bfloat16_rn(a);
    }
}

// ---------------- layernorm (512) ------------------------------------------
template <bool WF32>
__global__ void layernorm_kernel(const float* __restrict__ x,
                                 const float* __restrict__ w,
                                 const float* __restrict__ b,
                                 float* __restrict__ o,
                                 bf16* __restrict__ o16)
{
    const int n = blockIdx.x;
    const int t = threadIdx.x;
    float4 v = ((const float4*)(x + (size_t)n * DMQ))[t];
    float s = v.x + v.y + v.z + v.w;
    float q = v.x * v.x + v.y * v.y + v.z * v.z + v.w * v.w;
#pragma unroll
    for (int off = 16; off; off >>= 1) {
        s += __shfl_xor_sync(0xffffffffu, s, off);
        q += __shfl_xor_sync(0xffffffffu, q, off);
    }
    __shared__ float ss[4], sq[4];
    const int wid = t >> 5, lane = t & 31;
    if (lane == 0) { ss[wid] = s; sq[wid] = q; }
    __syncthreads();
    if (t == 0) {
        float S = ss[0] + ss[1] + ss[2] + ss[3];
        float Q = sq[0] + sq[1] + sq[2] + sq[3];
        float m = S * (1.f / DMQ);
        float var = Q * (1.f / DMQ) - m * m;
        ss[0] = m;
        sq[0] = rsqrtf(var + 1e-5f);
    }
    __syncthreads();
    const float m = ss[0], inv = sq[0];
    float4 wv = ((const float4*)w)[t];
    float4 bv = ((const float4*)b)[t];
    float4 r;
    r.x = (v.x - m) * inv * wv.x + bv.x;
    r.y = (v.y - m) * inv * wv.y + bv.y;
    r.z = (v.z - m) * inv * wv.z + bv.z;
    r.w = (v.w - m) * inv * wv.w + bv.w;
    if (WF32) ((float4*)(o + (size_t)n * DMQ))[t] = r;
    bf162* p16 = (bf162*)(o16 + (size_t)n * DMQ);
    p16[2 * t]     = __floats2bfloat162_rn(r.x, r.y);
    p16[2 * t + 1] = __floats2bfloat162_rn(r.z, r.w);
}

// ---------------- depthwise causal conv (DC=4) + bias + silu ----------------
__global__ void conv_silu_kernel(const bf16* __restrict__ xz,
                                 const float* __restrict__ cw,
                                 const float* __restrict__ cb,
                                 bf16* __restrict__ xs16)
{
    const int idx = blockIdx.x * blockDim.x + threadIdx.x;
    const int d = idx & 1023;
    const int n0 = (idx >> 10) << 2;
    const float4 w = ((const float4*)cw)[d];
    const float bias = cb[d];

    float xm3 = 0.f, xm2 = 0.f, xm1 = 0.f;
    if (n0 > 0) {
        xm3 = __bfloat162float(xz[(size_t)(n0 - 3) * 2048 + d]);
        xm2 = __bfloat162float(xz[(size_t)(n0 - 2) * 2048 + d]);
        xm1 = __bfloat162float(xz[(size_t)(n0 - 1) * 2048 + d]);
    }
    const float x0 = __bfloat162float(xz[(size_t)(n0 + 0) * 2048 + d]);
    const float x1 = __bfloat162float(xz[(size_t)(n0 + 1) * 2048 + d]);
    const float x2 = __bfloat162float(xz[(size_t)(n0 + 2) * 2048 + d]);
    const float x3 = __bfloat162float(xz[(size_t)(n0 + 3) * 2048 + d]);

    float y0 = bias + xm3 * w.x + xm2 * w.y + xm1 * w.z + x0 * w.w;
    float y1 = bias + xm2 * w.x + xm1 * w.y + x0  * w.z + x1 * w.w;
    float y2 = bias + xm1 * w.x + x0  * w.y + x1  * w.z + x2 * w.w;
    float y3 = bias + x0  * w.x + x1  * w.y + x2  * w.z + x3 * w.w;

    y0 = y0 / (1.f + __expf(-y0));
    y1 = y1 / (1.f + __expf(-y1));
    y2 = y2 / (1.f + __expf(-y2));
    y3 = y3 / (1.f + __expf(-y3));

    xs16[(size_t)(n0 + 0) * 1024 + d] = __float2bfloat16_rn(y0);
    xs16[(size_t)(n0 + 1) * 1024 + d] = __float2bfloat16_rn(y1);
    xs16[(size_t)(n0 + 2) * 1024 + d] = __float2bfloat16_rn(y2);
    xs16[(size_t)(n0 + 3) * 1024 + d] = __float2bfloat16_rn(y3);
}

// ---------------- chunked selective scan (bf16 delta/xs inputs) --------------
#define CHN 64
#define DGR 32

template <bool PASS3>
__global__ __launch_bounds__(512) void scan_chunk_kernel(
    const bf16* __restrict__ delta16,
    const bf16* __restrict__ xs16,
    const float* __restrict__ dbc,
    const bf16* __restrict__ xz16,
    const float* __restrict__ Alog,
    const float* __restrict__ Dv,
    const float* __restrict__ Hstart,
    float* __restrict__ Aend,
    float* __restrict__ Hend,
    bf16* __restrict__ y16)
{
    const int chunk = blockIdx.y;
    const int d0 = blockIdx.x * DGR;
    const int n0 = chunk * CHN;
    const int tid = threadIdx.x;
    const int s = tid & 15;
    const int dl = tid >> 4;
    const int d = d0 + dl;

    __shared__ float sh_delta[CHN][DGR];
    __shared__ float sh_xs[CHN][DGR];
    __shared__ float sh_z[CHN][DGR];
    __shared__ float sh_B[CHN][16];
    __shared__ float sh_C[CHN][16];

    for (int i = tid; i < CHN * DGR; i += 512) {
        const int r = i >> 5, c = i & 31;
        sh_delta[r][c] = __bfloat162float(delta16[(size_t)(n0 + r) * DIQ + d0 + c]);
        sh_xs[r][c]    = __bfloat162float(xs16[(size_t)(n0 + r) * DIQ + d0 + c]);
        if (PASS3)
            sh_z[r][c] = __bfloat162float(xz16[(size_t)(n0 + r) * 2048 + DIQ + d0 + c]);
    }
    for (int i = tid; i < CHN * 16; i += 512) {
        const int r = i >> 4, c = i & 15;
        sh_B[r][c] = dbc[(size_t)(n0 + r) * 64 + 32 + c];
        if (PASS3) sh_C[r][c] = dbc[(size_t)(n0 + r) * 64 + 48 + c];
    }
    __syncthreads();

    const float Ads = -expf(Alog[d * DSQ + s]);
    float h = 0.f, aP = 1.f;
    float dv = 0.f;
    if (PASS3) {
        h = Hstart[(size_t)(chunk * DIQ + d) * DSQ + s];
        dv = Dv[d];
    }

#pragma unroll 4
    for (int i = 0; i < CHN; i++) {
        const float dt = sh_delta[i][dl];
        const float xv = sh_xs[i][dl];
        const float a = __expf(dt * Ads);
        h = a * h + dt * sh_B[i][s] * xv;
        if (PASS3) {
            float v = h * sh_C[i][s];
            v += __shfl_xor_sync(0xffffffffu, v, 1);
            v += __shfl_xor_sync(0xffffffffu, v, 2);
            v += __shfl_xor_sync(0xffffffffu, v, 4);
            v += __shfl_xor_sync(0xffffffffu, v, 8);
            if (s == 0) {
                const float yv = v + dv * xv;
                const float zz = sh_z[i][dl];
                const float sig = 1.f / (1.f + __expf(-zz));
                y16[(size_t)(n0 + i) * DIQ + d] = __float2bfloat16_rn(yv * (zz * sig));
            }
        } else {
            aP *= a;
        }
    }
    if (!PASS3) {
        Aend[(size_t)(chunk * DIQ + d) * DSQ + s] = aP;
        Hend[(size_t)(chunk * DIQ + d) * DSQ + s] = h;
    }
}

__global__ void scan_combine_kernel(const float* __restrict__ Aend,
                                    const float* __restrict__ Hend,
                                    float* __restrict__ Hstart)
{
    const int idx = blockIdx.x * blockDim.x + threadIdx.x;
    float h = 0.f;
#pragma unroll 8
    for (int c = 0; c < 64; c++) {
        Hstart[(size_t)c * 16384 + idx] = h;
        h = Aend[(size_t)c * 16384 + idx] * h + Hend[(size_t)c * 16384 + idx];
    }
}

// ---------------- attention head --------------------------------------------
__global__ void asc_kernel(const float* __restrict__ k,
                           const float* __restrict__ w2,
                           const float* __restrict__ b2,
                           float* __restrict__ asc)
{
    const int gw = (blockIdx.x * blockDim.x + threadIdx.x) >> 5;
    const int lane = threadIdx.x & 31;
    const float4 a = ((const float4*)(k + (size_t)gw * 128))[lane];
    const float4 w = ((const float4*)w2)[lane];
    float s = a.x * w.x + a.y * w.y + a.z * w.z + a.w * w.w;
#pragma unroll
    for (int off = 16; off; off >>= 1) s += __shfl_xor_sync(0xffffffffu, s, off);
    if (lane == 0) asc[gw] = s + b2[0];
}

__global__ void softmax_kernel(const float* __restrict__ asc,
                               float* __restrict__ wts,
                               float* __restrict__ out)
{
    __shared__ float red[32];
    __shared__ float bc;
    const int t = threadIdx.x;
    const float4 v = ((const float4*)asc)[t];
    float mx = fmaxf(fmaxf(v.x, v.y), fmaxf(v.z, v.w));
#pragma unroll
    for (int off = 16; off; off >>= 1) mx = fmaxf(mx, __shfl_xor_sync(0xffffffffu, mx, off));
    if ((t & 31) == 0) red[t >> 5] = mx;
    __syncthreads();
    if (t < 32) {
        float m = red[t];
#pragma unroll
        for (int off = 16; off; off >>= 1) m = fmaxf(m, __shfl_xor_sync(0xffffffffu, m, off));
        if (t == 0) bc = m;
    }
    __syncthreads();
    const float M = bc;
    float e0 = __expf(v.x - M), e1 = __expf(v.y - M);
    float e2 = __expf(v.z - M), e3 = __expf(v.w - M);
    float s = e0 + e1 + e2 + e3;
#pragma unroll
    for (int off = 16; off; off >>= 1) s += __shfl_xor_sync(0xffffffffu, s, off);
    __syncthreads();
    if ((t & 31) == 0) red[t >> 5] = s;
    __syncthreads();
    if (t < 32) {
        float m = red[t];
#pragma unroll
        for (int off = 16; off; off >>= 1) m += __shfl_xor_sync(0xffffffffu, m, off);
        if (t == 0) bc = m;
    }
    __syncthreads();
    const float inv = 1.f / bc;
    e0 *= inv; e1 *= inv; e2 *= inv; e3 *= inv;
    ((float4*)wts)[t] = make_float4(e0, e1, e2, e3);
    out[2 + 4 * t + 0] = e0;
    out[2 + 4 * t + 1] = e1;
    out[2 + 4 * t + 2] = e2;
    out[2 + 4 * t + 3] = e3;
}

__global__ void pooled_kernel(const float* __restrict__ hf,
                              const float* __restrict__ wts,
                              float* __restrict__ pooled)
{
    const int d = threadIdx.x;
    const int n0 = blockIdx.x * 256;
    float acc = 0.f;
#pragma unroll 4
    for (int i = 0; i < 256; i++)
        acc += wts[n0 + i] * hf[(size_t)(n0 + i) * DMQ + d];
    atomicAdd(&pooled[d], acc);
}

__global__ void classifier_kernel(const float* __restrict__ pooled,
                                  const float* __restrict__ cw,
                                  const float* __restrict__ cb,
                                  float* __restrict__ out)
{
    const int lane = threadIdx.x;
    float s0 = 0.f, s1 = 0.f;
    for (int d = lane; d < DMQ; d += 32) {
        const float p = pooled[d];
        s0 += p * cw[d];
        s1 += p * cw[DMQ + d];
    }
#pragma unroll
    for (int off = 16; off; off >>= 1) {
        s0 += __shfl_xor_sync(0xffffffffu, s0, off);
        s1 += __shfl_xor_sync(0xffffffffu, s1, off);
    }
    if (lane == 0) {
        const float l0 = s0 + cb[0], l1 = s1 + cb[1];
        out[0] = 1.f / (1.f + expf(-l0));
        out[1] = 1.f / (1.f + expf(-l1));
        const float m = fmaxf(l0, l1);
        const float e0 = expf(l0 - m), e1 = expf(l1 - m);
        const float inv = 1.f / (e0 + e1);
        out[2 + NTOK] = e0 * inv;
        out[3 + NTOK] = e1 * inv;
        out[4 + NTOK] = (l1 > l0) ? 1.f : 0.f;
    }
}

// ---------------- orchestration ---------------------------------------------
static const int SMEM_N128_S4 = 4 * (128 + 128) * RSB;  // 81920
static const int SMEM_N128_S8 = 8 * (128 + 128) * RSB;  // 163840
static const int SMEM_N64_S4  = 4 * (128 + 64) * RSB;   // 61440
static const int SMEM_N64_S8  = 8 * (128 + 64) * RSB;   // 122880

extern "C" void kernel_launch(void* const* d_in, const int* in_sizes, int n_in,
                              void* d_out, int out_size)
{
    const float* x     = (const float*)d_in[0];
    const float* fc1_w = (const float*)d_in[1];
    const float* fc1_b = (const float*)d_in[2];
    const float* ln_w  = (const float*)d_in[3];
    const float* ln_b  = (const float*)d_in[4];
    const float* ipw   = (const float*)d_in[5];
    const float* cw    = (const float*)d_in[6];
    const float* cb    = (const float*)d_in[7];
    const float* xpw   = (const float*)d_in[8];
    const float* dtw   = (const float*)d_in[9];
    const float* dtb   = (const float*)d_in[10];
    const float* Alog  = (const float*)d_in[11];
    const float* Dv    = (const float*)d_in[12];
    const float* opw   = (const float*)d_in[13];
    const float* nw    = (const float*)d_in[14];
    const float* nb    = (const float*)d_in[15];
    const float* aw1   = (const float*)d_in[16];
    const float* ab1   = (const float*)d_in[17];
    const float* aw2   = (const float*)d_in[18];
    const float* ab2   = (const float*)d_in[19];
    const float* cwc   = (const float*)d_in[20];
    const float* cbc   = (const float*)d_in[21];
    float* out = (float*)d_out;

    float *p_h, *p_ln, *p_dbc, *p_dbcp;
    float *p_Aend, *p_Hend, *p_Hstart, *p_k, *p_asc, *p_wts, *p_pooled;
    bf16 *p_x16, *p_ln16, *p_xz16, *p_xs16, *p_delta16, *p_y16;
    bf16 *p_fc1w16, *p_ipw16, *p_xpw16, *p_opw16, *p_aw116;
    cudaGetSymbolAddress((void**)&p_h, g_h);
    cudaGetSymbolAddress((void**)&p_ln, g_ln);
    cudaGetSymbolAddress((void**)&p_dbc, g_dbc);
    cudaGetSymbolAddress((void**)&p_dbcp, g_dbcp);
    cudaGetSymbolAddress((void**)&p_Aend, g_Aend);
    cudaGetSymbolAddress((void**)&p_Hend, g_Hend);
    cudaGetSymbolAddress((void**)&p_Hstart, g_Hstart);
    cudaGetSymbolAddress((void**)&p_k, g_attnk);
    cudaGetSymbolAddress((void**)&p_asc, g_asc);
    cudaGetSymbolAddress((void**)&p_wts, g_wts);
    cudaGetSymbolAddress((void**)&p_pooled, g_pooled);
    cudaGetSymbolAddress((void**)&p_x16, g_x16);
    cudaGetSymbolAddress((void**)&p_ln16, g_ln16);
    cudaGetSymbolAddress((void**)&p_xz16, g_xz16);
    cudaGetSymbolAddress((void**)&p_xs16, g_xs16);
    cudaGetSymbolAddress((void**)&p_delta16, g_delta16);
    cudaGetSymbolAddress((void**)&p_y16, g_y16);
    cudaGetSymbolAddress((void**)&p_fc1w16, g_fc1w16);
    cudaGetSymbolAddress((void**)&p_ipw16, g_ipw16);
    cudaGetSymbolAddress((void**)&p_xpw16, g_xpw16);
    cudaGetSymbolAddress((void**)&p_opw16, g_opw16);
    cudaGetSymbolAddress((void**)&p_aw116, g_aw116);

    cudaFuncSetAttribute(gemm16_kernel<1, 128, 8, false, true,  false>, cudaFuncAttributeMaxDynamicSharedMemorySize, SMEM_N128_S8);
    cudaFuncSetAttribute(gemm16_kernel<3, 128, 8, false, true,  false>, cudaFuncAttributeMaxDynamicSharedMemorySize, SMEM_N128_S8);
    cudaFuncSetAttribute(gemm16_kernel<4, 64,  8, false, true,  false>, cudaFuncAttributeMaxDynamicSharedMemorySize, SMEM_N64_S8);
    cudaFuncSetAttribute(gemm16_kernel<0, 128, 4, true,  false, false>, cudaFuncAttributeMaxDynamicSharedMemorySize, SMEM_N128_S4);
    cudaFuncSetAttribute(gemm16_kernel<0, 64,  4, false, true,  true >, cudaFuncAttributeMaxDynamicSharedMemorySize, SMEM_N64_S4);

    // converts (3 launches)
    {
        int n0 = NTOK * F0Q / 4;
        cvt3_kernel<<<(n0 + 255) / 256, 256>>>(x, p_x16, n0,
                                               (const float*)0, (bf16*)0, 0,
                                               (const float*)0, (bf16*)0, 0);
        int a = DMQ * F0Q / 4, b = NLQ * 2 * DIQ * DMQ / 4, c = NLQ * DMQ * DIQ / 4;
        cvt3_kernel<<<(a + b + c + 255) / 256, 256>>>(fc1_w, p_fc1w16, a,
                                                      ipw, p_ipw16, b,
                                                      opw, p_opw16, c);
        int d = NLQ * 64 * DIQ / 4, f = 128 * DMQ / 4;
        cvt3_kernel<<<(d + f + 255) / 256, 256>>>(xpw, p_xpw16, d,
                                                  aw1, p_aw116, f,
                                                  (const float*)0, (bf16*)0, 0);
    }

    // h = relu(x @ fc1_w^T + fc1_b)   (8-stage: grid 128)
    gemm16_kernel<1, 128, 8, false, true, false><<<dim3(DMQ / 128, NTOK / 128), 256, SMEM_N128_S8>>>(
        p_x16, F0Q, p_fc1w16, F0Q, p_h, DMQ, (bf16*)0, fc1_b, 0, F0Q);

    for (int l = 0; l < NLQ; l++) {
        layernorm_kernel<false><<<NTOK, 128>>>(p_h, ln_w + l * DMQ, ln_b + l * DMQ,
                                               (float*)0, p_ln16);

        // xz = h_ln @ ipw^T  (bf16-only; 4-stage, grid 512)
        gemm16_kernel<0, 128, 4, true, false, false><<<dim3(2 * DIQ / 128, NTOK / 128), 256, SMEM_N128_S4>>>(
            p_ln16, DMQ, p_ipw16 + (size_t)l * 2 * DIQ * DMQ, DMQ, (float*)0, 2 * DIQ,
            p_xz16, (const float*)0, 0, DMQ);

        // xs = silu(conv(xin) + cb)  (bf16-only)
        conv_silu_kernel<<<NTOK * DIQ / 4 / 256, 256>>>(
            p_xz16, cw + l * DIQ * DCQ, cb + l * DIQ, p_xs16);

        // dbc = xs @ xpw^T via split-K x8
        gemm16_kernel<0, 64, 4, false, true, true><<<dim3(1, NTOK / 128, KSPLIT), 256, SMEM_N64_S4>>>(
            p_xs16, DIQ, p_xpw16 + (size_t)l * 64 * DIQ, DIQ, p_dbcp, 64,
            (bf16*)0, (const float*)0, NTOK * 64, DIQ / KSPLIT);
        dbc_reduce_kernel<<<NTOK * 64 / 4 / 256, 256>>>(p_dbcp, p_dbc);

        // delta = softplus(dbc[:, :32] @ dtw^T + dtb)  (dedicated kernel)
        delta_kernel<<<dim3(DIQ / 256, NTOK / 64), 256>>>(
            p_dbc, dtw + (size_t)l * DIQ * DTRQ, dtb + l * DIQ, p_delta16);

        // chunked selective scan (bf16 delta/xs)
        scan_chunk_kernel<false><<<dim3(DIQ / DGR, 64), 512>>>(
            p_delta16, p_xs16, p_dbc, (const bf16*)0,
            Alog + (size_t)l * DIQ * DSQ, (const float*)0, (const float*)0,
            p_Aend, p_Hend, (bf16*)0);
        scan_combine_kernel<<<DIQ * DSQ / 256, 256>>>(p_Aend, p_Hend, p_Hstart);
        scan_chunk_kernel<true><<<dim3(DIQ / DGR, 64), 512>>>(
            p_delta16, p_xs16, p_dbc, p_xz16,
            Alog + (size_t)l * DIQ * DSQ, Dv + l * DIQ, p_Hstart,
            (float*)0, (float*)0, p_y16);

        // h = h + y @ opw^T   (8-stage: grid 128)
        gemm16_kernel<3, 128, 8, false, true, false><<<dim3(DMQ / 128, NTOK / 128), 256, SMEM_N128_S8>>>(
            p_y16, DIQ, p_opw16 + (size_t)l * DMQ * DIQ, DIQ, p_h, DMQ,
            (bf16*)0, p_h, DMQ, DIQ);
    }

    layernorm_kernel<true><<<NTOK, 128>>>(p_h, nw, nb, p_ln, p_ln16);

    // k = tanh(h_f @ aw1^T + ab1)   (8-stage: grid 64)
    gemm16_kernel<4, 64, 8, false, true, false><<<dim3(2, NTOK / 128), 256, SMEM_N64_S8>>>(
        p_ln16, DMQ, p_aw116, DMQ, p_k, 128, (bf16*)0, ab1, 0, DMQ);

    asc_kernel<<<NTOK / 32, 1024>>>(p_k, aw2, ab2, p_asc);
    softmax_kernel<<<1, 1024>>>(p_asc, p_wts, out);

    cudaMemsetAsync(p_pooled, 0, DMQ * sizeof(float));
    pooled_kernel<<<16, 512>>>(p_ln, p_wts, p_pooled);
    classifier_kernel<<<1, 32>>>(p_pooled, cwc, cbc, out);
}

// round 15
// speedup vs baseline: 1.0489x; 1.0489x over previous
#include <cuda_runtime.h>
#include <cuda_bf16.h>
#include <math.h>
#include <stdint.h>

#define DMQ 512
#define DIQ 1024
#define DSQ 16
#define DCQ 4
#define DTRQ 32
#define NLQ 2
#define NTOK 4096
#define F0Q 1024
#define KSPLIT 8

typedef __nv_bfloat16 bf16;
typedef __nv_bfloat162 bf162;

// ---------------- scratch (device globals: allocation-free) ----------------
__device__ float g_h[NTOK * DMQ];
__device__ float g_ln[NTOK * DMQ];
__device__ float g_dbc[NTOK * 64];
__device__ float g_dbcp[KSPLIT * NTOK * 64];
__device__ float g_prefixH[64 * DIQ * DSQ];
__device__ int   g_flags[64 * 32];
__device__ float g_attnk[NTOK * 128];
__device__ float g_asc[NTOK];
__device__ float g_wts[NTOK];
__device__ float g_pooled[DMQ];
// bf16 buffers
__device__ bf16 g_x16[NTOK * F0Q];
__device__ bf16 g_ln16[NTOK * DMQ];
__device__ bf16 g_xz16[NTOK * 2 * DIQ];
__device__ bf16 g_xs16[NTOK * DIQ];
__device__ bf16 g_dbc16[NTOK * 64];
__device__ bf16 g_delta16[NTOK * DIQ];
__device__ bf16 g_y16[NTOK * DIQ];
__device__ bf16 g_fc1w16[DMQ * F0Q];
__device__ bf16 g_ipw16[NLQ * 2 * DIQ * DMQ];
__device__ bf16 g_xpw16[NLQ * 64 * DIQ];
__device__ bf16 g_dtw16[NLQ * DIQ * DTRQ];
__device__ bf16 g_opw16[NLQ * DMQ * DIQ];
__device__ bf16 g_aw116[128 * DMQ];

// ---------------- PTX helpers ------------------------------------------------
__device__ __forceinline__ uint32_t smem_u32(const void* p) {
    uint32_t a;
    asm("{ .reg .u64 t; cvta.to.shared.u64 t, %1; cvt.u32.u64 %0, t; }"
        : "=r"(a) : "l"(p));
    return a;
}

__device__ __forceinline__ void cp_async16(uint32_t dst, const void* src) {
    asm volatile("cp.async.ca.shared.global [%0], [%1], 16;"
                 :: "r"(dst), "l"(src) : "memory");
}
__device__ __forceinline__ void cp_commit() {
    asm volatile("cp.async.commit_group;" ::: "memory");
}
template <int N>
__device__ __forceinline__ void cp_wait() {
    asm volatile("cp.async.wait_group %0;" :: "n"(N) : "memory");
}

__device__ __forceinline__ void ldsm4(uint32_t* r, uint32_t addr) {
    asm volatile("ldmatrix.sync.aligned.m8n8.x4.shared.b16 {%0,%1,%2,%3}, [%4];"
                 : "=r"(r[0]), "=r"(r[1]), "=r"(r[2]), "=r"(r[3]) : "r"(addr));
}

__device__ __forceinline__ void mma_bf16(float* d, const uint32_t* a, const uint32_t* b) {
    asm volatile(
        "mma.sync.aligned.m16n8k16.row.col.f32.bf16.bf16.f32 "
        "{%0,%1,%2,%3}, {%4,%5,%6,%7}, {%8,%9}, {%0,%1,%2,%3};\n"
        : "+f"(d[0]), "+f"(d[1]), "+f"(d[2]), "+f"(d[3])
        : "r"(a[0]), "r"(a[1]), "r"(a[2]), "r"(a[3]), "r"(b[0]), "r"(b[1]));
}

// ---------------- fp32 -> bf16 convert (up to 3 regions per launch) ----------
__global__ void cvt3_kernel(const float* __restrict__ s0, bf16* __restrict__ d0, int n0,
                            const float* __restrict__ s1, bf16* __restrict__ d1, int n1,
                            const float* __restrict__ s2, bf16* __restrict__ d2, int n2)
{
    int i = blockIdx.x * blockDim.x + threadIdx.x;
    const float* s; bf16* d; int j;
    if (i < n0)               { s = s0; d = d0; j = i; }
    else if (i < n0 + n1)     { s = s1; d = d1; j = i - n0; }
    else if (i < n0 + n1 + n2){ s = s2; d = d2; j = i - n0 - n1; }
    else return;
    const float4 v = ((const float4*)s)[j];
    bf162* o = (bf162*)d;
    o[2 * j]     = __floats2bfloat162_rn(v.x, v.y);
    o[2 * j + 1] = __floats2bfloat162_rn(v.z, v.w);
}

// ---------------- bf16 tensor-core GEMM -------------------------------------
// C = A[M,K] * B[N,K]^T, bf16 row-major. CTA 128 x NT, 256 thr / 8 warps.
// BK=32, STAGES-deep cp.async ring. Rows padded to 80 B.
// EPI: 0 none, 1 bias+relu, 2 bias+softplus, 3 residual add, 4 bias+tanh
// SPLITK: grid.z = K-slice; fp32 partials at C + z*ldaux.
#define RSB 80

template <int EPI, int NT, int STAGES, bool WB16, bool WF32, bool SPLITK>
__global__ __launch_bounds__(256, (STAGES > 4 ? 1 : 2)) void gemm16_kernel(
    const bf16* __restrict__ A, int lda,
    const bf16* __restrict__ B, int ldb,
    float* __restrict__ C, int ldc,
    bf16* __restrict__ C16,
    const float* __restrict__ aux, int ldaux,
    int K)
{
    constexpr int WN = NT / 32;
    constexpr int WM = 8 / WN;
    constexpr int MI = 128 / (WM * 16);
    constexpr int NI = 4;
    constexpr int ASTG = 128 * RSB;
    constexpr int BSTG = NT * RSB;
    constexpr int STGB = ASTG + BSTG;

    extern __shared__ char smraw[];
    const uint32_t sbase = smem_u32(smraw);

    const int tid = threadIdx.x;
    const int wid = tid >> 5;
    const int lane = tid & 31;
    const int fr = lane >> 2;
    const int fc = lane & 3;
    const int wm = (wid % WM) * (MI * 16);
    const int wn = (wid / WM) * 32;
    const int bm = blockIdx.y * 128;
    const int bn = blockIdx.x * NT;

    if (SPLITK) {
        A += (size_t)blockIdx.z * K;
        B += (size_t)blockIdx.z * K;
    }

    float acc[MI][NI][4];
#pragma unroll
    for (int mi = 0; mi < MI; mi++)
#pragma unroll
        for (int ni = 0; ni < NI; ni++)
#pragma unroll
            for (int j = 0; j < 4; j++) acc[mi][ni][j] = 0.f;

    auto load_stage = [&](int stg, int c) {
        const int k0 = c << 5;
        const uint32_t abuf = sbase + stg * STGB;
        const uint32_t bbuf = abuf + ASTG;
#pragma unroll
        for (int i = 0; i < 2; i++) {
            const int u = tid + i * 256;
            const int r = u >> 2, q = u & 3;
            cp_async16(abuf + r * RSB + q * 16,
                       A + (size_t)(bm + r) * lda + k0 + q * 8);
        }
#pragma unroll
        for (int i = 0; i < NT / 64; i++) {
            const int u = tid + i * 256;
            const int r = u >> 2, q = u & 3;
            cp_async16(bbuf + r * RSB + q * 16,
                       B + (size_t)(bn + r) * ldb + k0 + q * 8);
        }
    };

    const int nch = K >> 5;
#pragma unroll
    for (int i = 0; i < STAGES - 1; i++) {
        if (i < nch) load_stage(i, i);
        cp_commit();
    }

    const int a_r = lane & 15, a_c8 = (lane >> 4) << 3;
    const int b_r = (lane & 7) + ((lane >> 4) << 3), b_c8 = lane & 8;

    for (int c = 0; c < nch; c++) {
        const int stg = c % STAGES;
        cp_wait<STAGES - 2>();
        __syncthreads();

        if (c + STAGES - 1 < nch) load_stage((c + STAGES - 1) % STAGES, c + STAGES - 1);
        cp_commit();

        const uint32_t abuf = sbase + stg * STGB;
        const uint32_t bbuf = abuf + ASTG;
#pragma unroll
        for (int kk = 0; kk < 2; kk++) {
            const int kb = kk << 4;
            uint32_t afr[MI][4], bfr[NI][2];
#pragma unroll
            for (int mi = 0; mi < MI; mi++)
                ldsm4(afr[mi],
                      abuf + (wm + mi * 16 + a_r) * RSB + (kb + a_c8) * 2);
#pragma unroll
            for (int n2 = 0; n2 < NI / 2; n2++) {
                uint32_t r4[4];
                ldsm4(r4, bbuf + (wn + n2 * 16 + b_r) * RSB + (kb + b_c8) * 2);
                bfr[2 * n2][0] = r4[0]; bfr[2 * n2][1] = r4[1];
                bfr[2 * n2 + 1][0] = r4[2]; bfr[2 * n2 + 1][1] = r4[3];
            }
#pragma unroll
            for (int mi = 0; mi < MI; mi++)
#pragma unroll
                for (int ni = 0; ni < NI; ni++)
                    mma_bf16(acc[mi][ni], afr[mi], bfr[ni]);
        }
    }

    float* Cw = C;
    if (SPLITK) Cw = C + (size_t)blockIdx.z * ldaux;

#pragma unroll
    for (int mi = 0; mi < MI; mi++) {
#pragma unroll
        for (int ni = 0; ni < NI; ni++) {
#pragma unroll
            for (int half = 0; half < 2; half++) {
                const int m = bm + wm + mi * 16 + fr + (half << 3);
                const int n = bn + wn + ni * 8 + (fc << 1);
                float v0 = acc[mi][ni][half * 2 + 0];
                float v1 = acc[mi][ni][half * 2 + 1];
                if (EPI == 1) {
                    v0 = fmaxf(v0 + aux[n], 0.f);
                    v1 = fmaxf(v1 + aux[n + 1], 0.f);
                } else if (EPI == 2) {
                    v0 += aux[n]; v1 += aux[n + 1];
                    v0 = (v0 > 20.f) ? v0 : log1pf(expf(v0));
                    v1 = (v1 > 20.f) ? v1 : log1pf(expf(v1));
                } else if (EPI == 3) {
                    const float2 r = *(const float2*)(aux + (size_t)m * ldaux + n);
                    v0 += r.x; v1 += r.y;
                } else if (EPI == 4) {
                    v0 = tanhf(v0 + aux[n]);
                    v1 = tanhf(v1 + aux[n + 1]);
                }
                if (SPLITK || WF32) {
                    float2 o; o.x = v0; o.y = v1;
                    *(float2*)(Cw + (size_t)m * ldc + n) = o;
                }
                if (!SPLITK && WB16)
                    *(bf162*)(C16 + (size_t)m * ldc + n) = __floats2bfloat162_rn(v0, v1);
            }
        }
    }
}

// ---------------- split-K reduce for dbc ------------------------------------
__global__ void dbc_reduce_kernel(const float* __restrict__ part,
                                  float* __restrict__ dbc,
                                  bf16* __restrict__ dbc16)
{
    const int i = blockIdx.x * blockDim.x + threadIdx.x;
    float4 s = ((const float4*)part)[i];
#pragma unroll
    for (int k = 1; k < KSPLIT; k++) {
        const float4 v = ((const float4*)(part + (size_t)k * NTOK * 64))[i];
        s.x += v.x; s.y += v.y; s.z += v.z; s.w += v.w;
    }
    ((float4*)dbc)[i] = s;
    bf162* o = (bf162*)dbc16;
    o[2 * i]     = __floats2bfloat162_rn(s.x, s.y);
    o[2 * i + 1] = __floats2bfloat162_rn(s.z, s.w);
}

// ---------------- layernorm (512) ------------------------------------------
template <bool WF32>
__global__ void layernorm_kernel(const float* __restrict__ x,
                                 const float* __restrict__ w,
                                 const float* __restrict__ b,
                                 float* __restrict__ o,
                                 bf16* __restrict__ o16)
{
    const int n = blockIdx.x;
    const int t = threadIdx.x;
    float4 v = ((const float4*)(x + (size_t)n * DMQ))[t];
    float s = v.x + v.y + v.z + v.w;
    float q = v.x * v.x + v.y * v.y + v.z * v.z + v.w * v.w;
#pragma unroll
    for (int off = 16; off; off >>= 1) {
        s += __shfl_xor_sync(0xffffffffu, s, off);
        q += __shfl_xor_sync(0xffffffffu, q, off);
    }
    __shared__ float ss[4], sq[4];
    const int wid = t >> 5, lane = t & 31;
    if (lane == 0) { ss[wid] = s; sq[wid] = q; }
    __syncthreads();
    if (t == 0) {
        float S = ss[0] + ss[1] + ss[2] + ss[3];
        float Q = sq[0] + sq[1] + sq[2] + sq[3];
        float m = S * (1.f / DMQ);
        float var = Q * (1.f / DMQ) - m * m;
        ss[0] = m;
        sq[0] = rsqrtf(var + 1e-5f);
    }
    __syncthreads();
    const float m = ss[0], inv = sq[0];
    float4 wv = ((const float4*)w)[t];
    float4 bv = ((const float4*)b)[t];
    float4 r;
    r.x = (v.x - m) * inv * wv.x + bv.x;
    r.y = (v.y - m) * inv * wv.y + bv.y;
    r.z = (v.z - m) * inv * wv.z + bv.z;
    r.w = (v.w - m) * inv * wv.w + bv.w;
    if (WF32) ((float4*)(o + (size_t)n * DMQ))[t] = r;
    bf162* p16 = (bf162*)(o16 + (size_t)n * DMQ);
    p16[2 * t]     = __floats2bfloat162_rn(r.x, r.y);
    p16[2 * t + 1] = __floats2bfloat162_rn(r.z, r.w);
}

// ---------------- depthwise causal conv (DC=4) + bias + silu ----------------
__global__ void conv_silu_kernel(const bf16* __restrict__ xz,
                                 const float* __restrict__ cw,
                                 const float* __restrict__ cb,
                                 bf16* __restrict__ xs16)
{
    const int idx = blockIdx.x * blockDim.x + threadIdx.x;
    const int d = idx & 1023;
    const int n0 = (idx >> 10) << 2;
    const float4 w = ((const float4*)cw)[d];
    const float bias = cb[d];

    float xm3 = 0.f, xm2 = 0.f, xm1 = 0.f;
    if (n0 > 0) {
        xm3 = __bfloat162float(xz[(size_t)(n0 - 3) * 2048 + d]);
        xm2 = __bfloat162float(xz[(size_t)(n0 - 2) * 2048 + d]);
        xm1 = __bfloat162float(xz[(size_t)(n0 - 1) * 2048 + d]);
    }
    const float x0 = __bfloat162float(xz[(size_t)(n0 + 0) * 2048 + d]);
    const float x1 = __bfloat162float(xz[(size_t)(n0 + 1) * 2048 + d]);
    const float x2 = __bfloat162float(xz[(size_t)(n0 + 2) * 2048 + d]);
    const float x3 = __bfloat162float(xz[(size_t)(n0 + 3) * 2048 + d]);

    float y0 = bias + xm3 * w.x + xm2 * w.y + xm1 * w.z + x0 * w.w;
    float y1 = bias + xm2 * w.x + xm1 * w.y + x0  * w.z + x1 * w.w;
    float y2 = bias + xm1 * w.x + x0  * w.y + x1  * w.z + x2 * w.w;
    float y3 = bias + x0  * w.x + x1  * w.y + x2  * w.z + x3 * w.w;

    y0 = y0 / (1.f + __expf(-y0));
    y1 = y1 / (1.f + __expf(-y1));
    y2 = y2 / (1.f + __expf(-y2));
    y3 = y3 / (1.f + __expf(-y3));

    xs16[(size_t)(n0 + 0) * 1024 + d] = __float2bfloat16_rn(y0);
    xs16[(size_t)(n0 + 1) * 1024 + d] = __float2bfloat16_rn(y1);
    xs16[(size_t)(n0 + 2) * 1024 + d] = __float2bfloat16_rn(y2);
    xs16[(size_t)(n0 + 3) * 1024 + d] = __float2bfloat16_rn(y3);
}

// ---------------- fused selective scan (decoupled lookback) ------------------
// grid (32 dgroups, 64 chunks) -- chunk is the SLOW index so predecessor
// blocks are launched first. Each block: load once, local recurrence,
// publish inclusive state, rerun from predecessor's prefix, emit y.
#define CHN 64
#define DGR 32

__global__ __launch_bounds__(512) void scan_fused_kernel(
    const bf16* __restrict__ delta16,
    const bf16* __restrict__ xs16,
    const float* __restrict__ dbc,
    const bf16* __restrict__ xz16,
    const float* __restrict__ Alog,
    const float* __restrict__ Dv,
    float* __restrict__ prefixH,     // [64][DIQ*DSQ], (chunk, d, s)
    int* __restrict__ flags,         // [64][32]
    bf16* __restrict__ y16)
{
    const int dgroup = blockIdx.x;
    const int chunk = blockIdx.y;
    const int d0 = dgroup * DGR;
    const int n0 = chunk * CHN;
    const int tid = threadIdx.x;
    const int s = tid & 15;
    const int dl = tid >> 4;
    const int d = d0 + dl;

    __shared__ float sh_delta[CHN][DGR];
    __shared__ float sh_xs[CHN][DGR];
    __shared__ float sh_z[CHN][DGR];
    __shared__ float sh_B[CHN][16];
    __shared__ float sh_C[CHN][16];

    for (int i = tid; i < CHN * DGR; i += 512) {
        const int r = i >> 5, c = i & 31;
        sh_delta[r][c] = __bfloat162float(delta16[(size_t)(n0 + r) * DIQ + d0 + c]);
        sh_xs[r][c]    = __bfloat162float(xs16[(size_t)(n0 + r) * DIQ + d0 + c]);
        sh_z[r][c]     = __bfloat162float(xz16[(size_t)(n0 + r) * 2048 + DIQ + d0 + c]);
    }
    for (int i = tid; i < CHN * 16; i += 512) {
        const int r = i >> 4, c = i & 15;
        sh_B[r][c] = dbc[(size_t)(n0 + r) * 64 + 32 + c];
        sh_C[r][c] = dbc[(size_t)(n0 + r) * 64 + 48 + c];
    }
    __syncthreads();

    const float Ads = -expf(Alog[d * DSQ + s]);

    // pass 1: local recurrence from zero
    float h = 0.f, aP = 1.f;
#pragma unroll 4
    for (int i = 0; i < CHN; i++) {
        const float dt = sh_delta[i][dl];
        const float a = __expf(dt * Ads);
        h = a * h + dt * sh_B[i][s] * sh_xs[i][dl];
        aP *= a;
    }

    // lookback: wait for predecessor chunk's inclusive state
    float hprev = 0.f;
    if (chunk > 0) {
        if (tid == 0) {
            while (atomicAdd(&flags[(chunk - 1) * 32 + dgroup], 0) == 0) {}
            __threadfence();
        }
        __syncthreads();
        hprev = prefixH[(size_t)(chunk - 1) * (DIQ * DSQ) + d * DSQ + s];
    }

    // publish inclusive state (release: store, fence, sync, flag)
    prefixH[(size_t)chunk * (DIQ * DSQ) + d * DSQ + s] = aP * hprev + h;
    __threadfence();
    __syncthreads();
    if (tid == 0) atomicExch(&flags[chunk * 32 + dgroup], 1);

    // pass 3: rerun from hprev, emit y
    const float dv = Dv[d];
    h = hprev;
#pragma unroll 4
    for (int i = 0; i < CHN; i++) {
        const float dt = sh_delta[i][dl];
        const float xv = sh_xs[i][dl];
        const float a = __expf(dt * Ads);
        h = a * h + dt * sh_B[i][s] * xv;
        float v = h * sh_C[i][s];
        v += __shfl_xor_sync(0xffffffffu, v, 1);
        v += __shfl_xor_sync(0xffffffffu, v, 2);
        v += __shfl_xor_sync(0xffffffffu, v, 4);
        v += __shfl_xor_sync(0xffffffffu, v, 8);
        if (s == 0) {
            const float yv = v + dv * xv;
            const float zz = sh_z[i][dl];
            const float sig = 1.f / (1.f + __expf(-zz));
            y16[(size_t)(n0 + i) * DIQ + d] = __float2bfloat16_rn(yv * (zz * sig));
        }
    }
}

// ---------------- attention head --------------------------------------------
__global__ void asc_kernel(const float* __restrict__ k,
                           const float* __restrict__ w2,
                           const float* __restrict__ b2,
                           float* __restrict__ asc)
{
    const int gw = (blockIdx.x * blockDim.x + threadIdx.x) >> 5;
    const int lane = threadIdx.x & 31;
    const float4 a = ((const float4*)(k + (size_t)gw * 128))[lane];
    const float4 w = ((const float4*)w2)[lane];
    float s = a.x * w.x + a.y * w.y + a.z * w.z + a.w * w.w;
#pragma unroll
    for (int off = 16; off; off >>= 1) s += __shfl_xor_sync(0xffffffffu, s, off);
    if (lane == 0) asc[gw] = s + b2[0];
}

__global__ void softmax_kernel(const float* __restrict__ asc,
                               float* __restrict__ wts,
                               float* __restrict__ out)
{
    __shared__ float red[32];
    __shared__ float bc;
    const int t = threadIdx.x;
    const float4 v = ((const float4*)asc)[t];
    float mx = fmaxf(fmaxf(v.x, v.y), fmaxf(v.z, v.w));
#pragma unroll
    for (int off = 16; off; off >>= 1) mx = fmaxf(mx, __shfl_xor_sync(0xffffffffu, mx, off));
    if ((t & 31) == 0) red[t >> 5] = mx;
    __syncthreads();
    if (t < 32) {
        float m = red[t];
#pragma unroll
        for (int off = 16; off; off >>= 1) m = fmaxf(m, __shfl_xor_sync(0xffffffffu, m, off));
        if (t == 0) bc = m;
    }
    __syncthreads();
    const float M = bc;
    float e0 = __expf(v.x - M), e1 = __expf(v.y - M);
    float e2 = __expf(v.z - M), e3 = __expf(v.w - M);
    float s = e0 + e1 + e2 + e3;
#pragma unroll
    for (int off = 16; off; off >>= 1) s += __shfl_xor_sync(0xffffffffu, s, off);
    __syncthreads();
    if ((t & 31) == 0) red[t >> 5] = s;
    __syncthreads();
    if (t < 32) {
        float m = red[t];
#pragma unroll
        for (int off = 16; off; off >>= 1) m += __shfl_xor_sync(0xffffffffu, m, off);
        if (t == 0) bc = m;
    }
    __syncthreads();
    const float inv = 1.f / bc;
    e0 *= inv; e1 *= inv; e2 *= inv; e3 *= inv;
    ((float4*)wts)[t] = make_float4(e0, e1, e2, e3);
    out[2 + 4 * t + 0] = e0;
    out[2 + 4 * t + 1] = e1;
    out[2 + 4 * t + 2] = e2;
    out[2 + 4 * t + 3] = e3;
}

__global__ void pooled_kernel(const float* __restrict__ hf,
                              const float* __restrict__ wts,
                              float* __restrict__ pooled)
{
    const int d = threadIdx.x;
    const int n0 = blockIdx.x * 256;
    float acc = 0.f;
#pragma unroll 4
    for (int i = 0; i < 256; i++)
        acc += wts[n0 + i] * hf[(size_t)(n0 + i) * DMQ + d];
    atomicAdd(&pooled[d], acc);
}

__global__ void classifier_kernel(const float* __restrict__ pooled,
                                  const float* __restrict__ cw,
                                  const float* __restrict__ cb,
                                  float* __restrict__ out)
{
    const int lane = threadIdx.x;
    float s0 = 0.f, s1 = 0.f;
    for (int d = lane; d < DMQ; d += 32) {
        const float p = pooled[d];
        s0 += p * cw[d];
        s1 += p * cw[DMQ + d];
    }
#pragma unroll
    for (int off = 16; off; off >>= 1) {
        s0 += __shfl_xor_sync(0xffffffffu, s0, off);
        s1 += __shfl_xor_sync(0xffffffffu, s1, off);
    }
    if (lane == 0) {
        const float l0 = s0 + cb[0], l1 = s1 + cb[1];
        out[0] = 1.f / (1.f + expf(-l0));
        out[1] = 1.f / (1.f + expf(-l1));
        const float m = fmaxf(l0, l1);
        const float e0 = expf(l0 - m), e1 = expf(l1 - m);
        const float inv = 1.f / (e0 + e1);
        out[2 + NTOK] = e0 * inv;
        out[3 + NTOK] = e1 * inv;
        out[4 + NTOK] = (l1 > l0) ? 1.f : 0.f;
    }
}

// ---------------- orchestration ---------------------------------------------
static const int SMEM_N128_S4 = 4 * (128 + 128) * RSB;  // 81920
static const int SMEM_N128_S8 = 8 * (128 + 128) * RSB;  // 163840
static const int SMEM_N64_S4  = 4 * (128 + 64) * RSB;   // 61440
static const int SMEM_N64_S8  = 8 * (128 + 64) * RSB;   // 122880

extern "C" void kernel_launch(void* const* d_in, const int* in_sizes, int n_in,
                              void* d_out, int out_size)
{
    const float* x     = (const float*)d_in[0];
    const float* fc1_w = (const float*)d_in[1];
    const float* fc1_b = (const float*)d_in[2];
    const float* ln_w  = (const float*)d_in[3];
    const float* ln_b  = (const float*)d_in[4];
    const float* ipw   = (const float*)d_in[5];
    const float* cw    = (const float*)d_in[6];
    const float* cb    = (const float*)d_in[7];
    const float* xpw   = (const float*)d_in[8];
    const float* dtw   = (const float*)d_in[9];
    const float* dtb   = (const float*)d_in[10];
    const float* Alog  = (const float*)d_in[11];
    const float* Dv    = (const float*)d_in[12];
    const float* opw   = (const float*)d_in[13];
    const float* nw    = (const float*)d_in[14];
    const float* nb    = (const float*)d_in[15];
    const float* aw1   = (const float*)d_in[16];
    const float* ab1   = (const float*)d_in[17];
    const float* aw2   = (const float*)d_in[18];
    const float* ab2   = (const float*)d_in[19];
    const float* cwc   = (const float*)d_in[20];
    const float* cbc   = (const float*)d_in[21];
    float* out = (float*)d_out;

    float *p_h, *p_ln, *p_dbc, *p_dbcp, *p_prefixH;
    int *p_flags;
    float *p_k, *p_asc, *p_wts, *p_pooled;
    bf16 *p_x16, *p_ln16, *p_xz16, *p_xs16, *p_dbc16, *p_delta16, *p_y16;
    bf16 *p_fc1w16, *p_ipw16, *p_xpw16, *p_dtw16, *p_opw16, *p_aw116;
    cudaGetSymbolAddress((void**)&p_h, g_h);
    cudaGetSymbolAddress((void**)&p_ln, g_ln);
    cudaGetSymbolAddress((void**)&p_dbc, g_dbc);
    cudaGetSymbolAddress((void**)&p_dbcp, g_dbcp);
    cudaGetSymbolAddress((void**)&p_prefixH, g_prefixH);
    cudaGetSymbolAddress((void**)&p_flags, g_flags);
    cudaGetSymbolAddress((void**)&p_k, g_attnk);
    cudaGetSymbolAddress((void**)&p_asc, g_asc);
    cudaGetSymbolAddress((void**)&p_wts, g_wts);
    cudaGetSymbolAddress((void**)&p_pooled, g_pooled);
    cudaGetSymbolAddress((void**)&p_x16, g_x16);
    cudaGetSymbolAddress((void**)&p_ln16, g_ln16);
    cudaGetSymbolAddress((void**)&p_xz16, g_xz16);
    cudaGetSymbolAddress((void**)&p_xs16, g_xs16);
    cudaGetSymbolAddress((void**)&p_dbc16, g_dbc16);
    cudaGetSymbolAddress((void**)&p_delta16, g_delta16);
    cudaGetSymbolAddress((void**)&p_y16, g_y16);
    cudaGetSymbolAddress((void**)&p_fc1w16, g_fc1w16);
    cudaGetSymbolAddress((void**)&p_ipw16, g_ipw16);
    cudaGetSymbolAddress((void**)&p_xpw16, g_xpw16);
    cudaGetSymbolAddress((void**)&p_dtw16, g_dtw16);
    cudaGetSymbolAddress((void**)&p_opw16, g_opw16);
    cudaGetSymbolAddress((void**)&p_aw116, g_aw116);

    cudaFuncSetAttribute(gemm16_kernel<1, 128, 8, false, true,  false>, cudaFuncAttributeMaxDynamicSharedMemorySize, SMEM_N128_S8);
    cudaFuncSetAttribute(gemm16_kernel<3, 128, 8, false, true,  false>, cudaFuncAttributeMaxDynamicSharedMemorySize, SMEM_N128_S8);
    cudaFuncSetAttribute(gemm16_kernel<4, 64,  8, false, true,  false>, cudaFuncAttributeMaxDynamicSharedMemorySize, SMEM_N64_S8);
    cudaFuncSetAttribute(gemm16_kernel<0, 128, 4, true,  false, false>, cudaFuncAttributeMaxDynamicSharedMemorySize, SMEM_N128_S4);
    cudaFuncSetAttribute(gemm16_kernel<2, 128, 4, true,  false, false>, cudaFuncAttributeMaxDynamicSharedMemorySize, SMEM_N128_S4);
    cudaFuncSetAttribute(gemm16_kernel<0, 64,  4, false, true,  true >, cudaFuncAttributeMaxDynamicSharedMemorySize, SMEM_N64_S4);

    // converts (3 launches)
    {
        int n0 = NTOK * F0Q / 4;
        cvt3_kernel<<<(n0 + 255) / 256, 256>>>(x, p_x16, n0,
                                               (const float*)0, (bf16*)0, 0,
                                               (const float*)0, (bf16*)0, 0);
        int a = DMQ * F0Q / 4, b = NLQ * 2 * DIQ * DMQ / 4, c = NLQ * DMQ * DIQ / 4;
        cvt3_kernel<<<(a + b + c + 255) / 256, 256>>>(fc1_w, p_fc1w16, a,
                                                      ipw, p_ipw16, b,
                                                      opw, p_opw16, c);
        int d = NLQ * 64 * DIQ / 4, e = NLQ * DIQ * DTRQ / 4, f = 128 * DMQ / 4;
        cvt3_kernel<<<(d + e + f + 255) / 256, 256>>>(xpw, p_xpw16, d,
                                                      dtw, p_dtw16, e,
                                                      aw1, p_aw116, f);
    }

    // h = relu(x @ fc1_w^T + fc1_b)   (8-stage: grid 128)
    gemm16_kernel<1, 128, 8, false, true, false><<<dim3(DMQ / 128, NTOK / 128), 256, SMEM_N128_S8>>>(
        p_x16, F0Q, p_fc1w16, F0Q, p_h, DMQ, (bf16*)0, fc1_b, 0, F0Q);

    for (int l = 0; l < NLQ; l++) {
        layernorm_kernel<false><<<NTOK, 128>>>(p_h, ln_w + l * DMQ, ln_b + l * DMQ,
                                               (float*)0, p_ln16);

        // xz = h_ln @ ipw^T  (bf16-only; 4-stage, grid 512)
        gemm16_kernel<0, 128, 4, true, false, false><<<dim3(2 * DIQ / 128, NTOK / 128), 256, SMEM_N128_S4>>>(
            p_ln16, DMQ, p_ipw16 + (size_t)l * 2 * DIQ * DMQ, DMQ, (float*)0, 2 * DIQ,
            p_xz16, (const float*)0, 0, DMQ);

        // xs = silu(conv(xin) + cb)  (bf16-only)
        conv_silu_kernel<<<NTOK * DIQ / 4 / 256, 256>>>(
            p_xz16, cw + l * DIQ * DCQ, cb + l * DIQ, p_xs16);

        // dbc = xs @ xpw^T via split-K x8
        gemm16_kernel<0, 64, 4, false, true, true><<<dim3(1, NTOK / 128, KSPLIT), 256, SMEM_N64_S4>>>(
            p_xs16, DIQ, p_xpw16 + (size_t)l * 64 * DIQ, DIQ, p_dbcp, 64,
            (bf16*)0, (const float*)0, NTOK * 64, DIQ / KSPLIT);
        dbc_reduce_kernel<<<NTOK * 64 / 4 / 256, 256>>>(p_dbcp, p_dbc, p_dbc16);

        // delta = softplus(dt @ dtw^T + dtb)  (bf16-only output)
        gemm16_kernel<2, 128, 4, true, false, false><<<dim3(DIQ / 128, NTOK / 128), 256, SMEM_N128_S4>>>(
            p_dbc16, 64, p_dtw16 + (size_t)l * DIQ * DTRQ, DTRQ, (float*)0, DIQ,
            p_delta16, dtb + l * DIQ, 0, DTRQ);

        // fused single-pass scan with decoupled lookback
        cudaMemsetAsync(p_flags, 0, 64 * 32 * sizeof(int));
        scan_fused_kernel<<<dim3(DGR, 64), 512>>>(
            p_delta16, p_xs16, p_dbc, p_xz16,
            Alog + (size_t)l * DIQ * DSQ, Dv + l * DIQ,
            p_prefixH, p_flags, p_y16);

        // h = h + y @ opw^T   (8-stage: grid 128)
        gemm16_kernel<3, 128, 8, false, true, false><<<dim3(DMQ / 128, NTOK / 128), 256, SMEM_N128_S8>>>(
            p_y16, DIQ, p_opw16 + (size_t)l * DMQ * DIQ, DIQ, p_h, DMQ,
            (bf16*)0, p_h, DMQ, DIQ);
    }

    layernorm_kernel<true><<<NTOK, 128>>>(p_h, nw, nb, p_ln, p_ln16);

    // k = tanh(h_f @ aw1^T + ab1)   (8-stage: grid 64)
    gemm16_kernel<4, 64, 8, false, true, false><<<dim3(2, NTOK / 128), 256, SMEM_N64_S8>>>(
        p_ln16, DMQ, p_aw116, DMQ, p_k, 128, (bf16*)0, ab1, 0, DMQ);

    asc_kernel<<<NTOK / 32, 1024>>>(p_k, aw2, ab2, p_asc);
    softmax_kernel<<<1, 1024>>>(p_asc, p_wts, out);

    cudaMemsetAsync(p_pooled, 0, DMQ * sizeof(float));
    pooled_kernel<<<16, 512>>>(p_ln, p_wts, p_pooled);
    classifier_kernel<<<1, 32>>>(p_pooled, cwc, cbc, out);
}

// round 16
// speedup vs baseline: 1.0548x; 1.0056x over previous
#include <cuda_runtime.h>
#include <cuda_bf16.h>
#include <math.h>
#include <stdint.h>

#define DMQ 512
#define DIQ 1024
#define DSQ 16
#define DCQ 4
#define DTRQ 32
#define NLQ 2
#define NTOK 4096
#define F0Q 1024
#define KSPLIT 8

typedef __nv_bfloat16 bf16;
typedef __nv_bfloat162 bf162;

// ---------------- scratch (device globals: allocation-free) ----------------
__device__ float g_h[NTOK * DMQ];
__device__ float g_ln[NTOK * DMQ];
__device__ float g_dbc[NTOK * 64];
__device__ float g_dbcp[KSPLIT * NTOK * 64];
__device__ float g_Aend[64 * DIQ * DSQ];
__device__ float g_Hend[64 * DIQ * DSQ];
__device__ float g_Hstart[64 * DIQ * DSQ];
__device__ float g_attnk[NTOK * 128];
__device__ float g_asc[NTOK];
__device__ float g_wts[NTOK];
__device__ float g_pooled[DMQ];
// bf16 buffers
__device__ bf16 g_x16[NTOK * F0Q];
__device__ bf16 g_ln16[NTOK * DMQ];
__device__ bf16 g_xz16[NTOK * 2 * DIQ];
__device__ bf16 g_xs16[NTOK * DIQ];
__device__ bf16 g_dbc16[NTOK * 64];
__device__ bf16 g_delta16[NTOK * DIQ];
__device__ bf16 g_y16[NTOK * DIQ];
__device__ bf16 g_fc1w16[DMQ * F0Q];
__device__ bf16 g_ipw16[NLQ * 2 * DIQ * DMQ];
__device__ bf16 g_xpw16[NLQ * 64 * DIQ];
__device__ bf16 g_dtw16[NLQ * DIQ * DTRQ];
__device__ bf16 g_opw16[NLQ * DMQ * DIQ];
__device__ bf16 g_aw116[128 * DMQ];

// ---------------- PTX helpers ------------------------------------------------
__device__ __forceinline__ uint32_t smem_u32(const void* p) {
    uint32_t a;
    asm("{ .reg .u64 t; cvta.to.shared.u64 t, %1; cvt.u32.u64 %0, t; }"
        : "=r"(a) : "l"(p));
    return a;
}

__device__ __forceinline__ void cp_async16(uint32_t dst, const void* src) {
    asm volatile("cp.async.ca.shared.global [%0], [%1], 16;"
                 :: "r"(dst), "l"(src) : "memory");
}
__device__ __forceinline__ void cp_commit() {
    asm volatile("cp.async.commit_group;" ::: "memory");
}
template <int N>
__device__ __forceinline__ void cp_wait() {
    asm volatile("cp.async.wait_group %0;" :: "n"(N) : "memory");
}

__device__ __forceinline__ void ldsm4(uint32_t* r, uint32_t addr) {
    asm volatile("ldmatrix.sync.aligned.m8n8.x4.shared.b16 {%0,%1,%2,%3}, [%4];"
                 : "=r"(r[0]), "=r"(r[1]), "=r"(r[2]), "=r"(r[3]) : "r"(addr));
}

__device__ __forceinline__ void mma_bf16(float* d, const uint32_t* a, const uint32_t* b) {
    asm volatile(
        "mma.sync.aligned.m16n8k16.row.col.f32.bf16.bf16.f32 "
        "{%0,%1,%2,%3}, {%4,%5,%6,%7}, {%8,%9}, {%0,%1,%2,%3};\n"
        : "+f"(d[0]), "+f"(d[1]), "+f"(d[2]), "+f"(d[3])
        : "r"(a[0]), "r"(a[1]), "r"(a[2]), "r"(a[3]), "r"(b[0]), "r"(b[1]));
}

// ---------------- fp32 -> bf16 convert (up to 3 regions per launch) ----------
__global__ void cvt3_kernel(const float* __restrict__ s0, bf16* __restrict__ d0, int n0,
                            const float* __restrict__ s1, bf16* __restrict__ d1, int n1,
                            const float* __restrict__ s2, bf16* __restrict__ d2, int n2)
{
    int i = blockIdx.x * blockDim.x + threadIdx.x;
    const float* s; bf16* d; int j;
    if (i < n0)               { s = s0; d = d0; j = i; }
    else if (i < n0 + n1)     { s = s1; d = d1; j = i - n0; }
    else if (i < n0 + n1 + n2){ s = s2; d = d2; j = i - n0 - n1; }
    else return;
    const float4 v = ((const float4*)s)[j];
    bf162* o = (bf162*)d;
    o[2 * j]     = __floats2bfloat162_rn(v.x, v.y);
    o[2 * j + 1] = __floats2bfloat162_rn(v.z, v.w);
}

// ---------------- bf16 tensor-core GEMM -------------------------------------
// C = A[M,K] * B[N,K]^T, bf16 row-major. CTA 128 x NT, 256 thr / 8 warps.
// BK=32, STAGES-deep cp.async ring. Rows padded to 80 B.
// STAGES>4 (1 CTA/SM): fragment loads for the WHOLE chunk are batched before
// any mma, decoupling LDSM latency from the mma stream.
// EPI: 0 none, 1 bias+relu, 2 bias+softplus, 3 residual add, 4 bias+tanh
// SPLITK: grid.z = K-slice; fp32 partials at C + z*ldaux.
#define RSB 80

template <int EPI, int NT, int STAGES, bool WB16, bool WF32, bool SPLITK>
__global__ __launch_bounds__(256, (STAGES > 4 ? 1 : 2)) void gemm16_kernel(
    const bf16* __restrict__ A, int lda,
    const bf16* __restrict__ B, int ldb,
    float* __restrict__ C, int ldc,
    bf16* __restrict__ C16,
    const float* __restrict__ aux, int ldaux,
    int K)
{
    constexpr int WN = NT / 32;
    constexpr int WM = 8 / WN;
    constexpr int MI = 128 / (WM * 16);
    constexpr int NI = 4;
    constexpr int ASTG = 128 * RSB;
    constexpr int BSTG = NT * RSB;
    constexpr int STGB = ASTG + BSTG;

    extern __shared__ char smraw[];
    const uint32_t sbase = smem_u32(smraw);

    const int tid = threadIdx.x;
    const int wid = tid >> 5;
    const int lane = tid & 31;
    const int fr = lane >> 2;
    const int fc = lane & 3;
    const int wm = (wid % WM) * (MI * 16);
    const int wn = (wid / WM) * 32;
    const int bm = blockIdx.y * 128;
    const int bn = blockIdx.x * NT;

    if (SPLITK) {
        A += (size_t)blockIdx.z * K;
        B += (size_t)blockIdx.z * K;
    }

    float acc[MI][NI][4];
#pragma unroll
    for (int mi = 0; mi < MI; mi++)
#pragma unroll
        for (int ni = 0; ni < NI; ni++)
#pragma unroll
            for (int j = 0; j < 4; j++) acc[mi][ni][j] = 0.f;

    auto load_stage = [&](int stg, int c) {
        const int k0 = c << 5;
        const uint32_t abuf = sbase + stg * STGB;
        const uint32_t bbuf = abuf + ASTG;
#pragma unroll
        for (int i = 0; i < 2; i++) {
            const int u = tid + i * 256;
            const int r = u >> 2, q = u & 3;
            cp_async16(abuf + r * RSB + q * 16,
                       A + (size_t)(bm + r) * lda + k0 + q * 8);
        }
#pragma unroll
        for (int i = 0; i < NT / 64; i++) {
            const int u = tid + i * 256;
            const int r = u >> 2, q = u & 3;
            cp_async16(bbuf + r * RSB + q * 16,
                       B + (size_t)(bn + r) * ldb + k0 + q * 8);
        }
    };

    const int nch = K >> 5;
#pragma unroll
    for (int i = 0; i < STAGES - 1; i++) {
        if (i < nch) load_stage(i, i);
        cp_commit();
    }

    const int a_r = lane & 15, a_c8 = (lane >> 4) << 3;
    const int b_r = (lane & 7) + ((lane >> 4) << 3), b_c8 = lane & 8;

    for (int c = 0; c < nch; c++) {
        const int stg = c % STAGES;
        cp_wait<STAGES - 2>();
        __syncthreads();

        if (c + STAGES - 1 < nch) load_stage((c + STAGES - 1) % STAGES, c + STAGES - 1);
        cp_commit();

        const uint32_t abuf = sbase + stg * STGB;
        const uint32_t bbuf = abuf + ASTG;

        if (STAGES > 4) {
            // batched: all fragment loads for the chunk, then all mmas
            uint32_t afr[2][MI][4], bfr[2][NI][2];
#pragma unroll
            for (int kk = 0; kk < 2; kk++) {
                const int kb = kk << 4;
#pragma unroll
                for (int mi = 0; mi < MI; mi++)
                    ldsm4(afr[kk][mi],
                          abuf + (wm + mi * 16 + a_r) * RSB + (kb + a_c8) * 2);
#pragma unroll
                for (int n2 = 0; n2 < NI / 2; n2++) {
                    uint32_t r4[4];
                    ldsm4(r4, bbuf + (wn + n2 * 16 + b_r) * RSB + (kb + b_c8) * 2);
                    bfr[kk][2 * n2][0] = r4[0]; bfr[kk][2 * n2][1] = r4[1];
                    bfr[kk][2 * n2 + 1][0] = r4[2]; bfr[kk][2 * n2 + 1][1] = r4[3];
                }
            }
#pragma unroll
            for (int kk = 0; kk < 2; kk++)
#pragma unroll
                for (int mi = 0; mi < MI; mi++)
#pragma unroll
                    for (int ni = 0; ni < NI; ni++)
                        mma_bf16(acc[mi][ni], afr[kk][mi], bfr[kk][ni]);
        } else {
#pragma unroll
            for (int kk = 0; kk < 2; kk++) {
                const int kb = kk << 4;
                uint32_t afr[MI][4], bfr[NI][2];
#pragma unroll
                for (int mi = 0; mi < MI; mi++)
                    ldsm4(afr[mi],
                          abuf + (wm + mi * 16 + a_r) * RSB + (kb + a_c8) * 2);
#pragma unroll
                for (int n2 = 0; n2 < NI / 2; n2++) {
                    uint32_t r4[4];
                    ldsm4(r4, bbuf + (wn + n2 * 16 + b_r) * RSB + (kb + b_c8) * 2);
                    bfr[2 * n2][0] = r4[0]; bfr[2 * n2][1] = r4[1];
                    bfr[2 * n2 + 1][0] = r4[2]; bfr[2 * n2 + 1][1] = r4[3];
                }
#pragma unroll
                for (int mi = 0; mi < MI; mi++)
#pragma unroll
                    for (int ni = 0; ni < NI; ni++)
                        mma_bf16(acc[mi][ni], afr[mi], bfr[ni]);
            }
        }
    }

    float* Cw = C;
    if (SPLITK) Cw = C + (size_t)blockIdx.z * ldaux;

#pragma unroll
    for (int mi = 0; mi < MI; mi++) {
#pragma unroll
        for (int ni = 0; ni < NI; ni++) {
#pragma unroll
            for (int half = 0; half < 2; half++) {
                const int m = bm + wm + mi * 16 + fr + (half << 3);
                const int n = bn + wn + ni * 8 + (fc << 1);
                float v0 = acc[mi][ni][half * 2 + 0];
                float v1 = acc[mi][ni][half * 2 + 1];
                if (EPI == 1) {
                    v0 = fmaxf(v0 + aux[n], 0.f);
                    v1 = fmaxf(v1 + aux[n + 1], 0.f);
                } else if (EPI == 2) {
                    v0 += aux[n]; v1 += aux[n + 1];
                    v0 = (v0 > 20.f) ? v0 : log1pf(expf(v0));
                    v1 = (v1 > 20.f) ? v1 : log1pf(expf(v1));
                } else if (EPI == 3) {
                    const float2 r = *(const float2*)(aux + (size_t)m * ldaux + n);
                    v0 += r.x; v1 += r.y;
                } else if (EPI == 4) {
                    v0 = tanhf(v0 + aux[n]);
                    v1 = tanhf(v1 + aux[n + 1]);
                }
                if (SPLITK || WF32) {
                    float2 o; o.x = v0; o.y = v1;
                    *(float2*)(Cw + (size_t)m * ldc + n) = o;
                }
                if (!SPLITK && WB16)
                    *(bf162*)(C16 + (size_t)m * ldc + n) = __floats2bfloat162_rn(v0, v1);
            }
        }
    }
}

// ---------------- split-K reduce for dbc ------------------------------------
__global__ void dbc_reduce_kernel(const float* __restrict__ part,
                                  float* __restrict__ dbc,
                                  bf16* __restrict__ dbc16)
{
    const int i = blockIdx.x * blockDim.x + threadIdx.x;
    float4 s = ((const float4*)part)[i];
#pragma unroll
    for (int k = 1; k < KSPLIT; k++) {
        const float4 v = ((const float4*)(part + (size_t)k * NTOK * 64))[i];
        s.x += v.x; s.y += v.y; s.z += v.z; s.w += v.w;
    }
    ((float4*)dbc)[i] = s;
    bf162* o = (bf162*)dbc16;
    o[2 * i]     = __floats2bfloat162_rn(s.x, s.y);
    o[2 * i + 1] = __floats2bfloat162_rn(s.z, s.w);
}

// ---------------- layernorm (512) ------------------------------------------
template <bool WF32>
__global__ void layernorm_kernel(const float* __restrict__ x,
                                 const float* __restrict__ w,
                                 const float* __restrict__ b,
                                 float* __restrict__ o,
                                 bf16* __restrict__ o16)
{
    const int n = blockIdx.x;
    const int t = threadIdx.x;
    float4 v = ((const float4*)(x + (size_t)n * DMQ))[t];
    float s = v.x + v.y + v.z + v.w;
    float q = v.x * v.x + v.y * v.y + v.z * v.z + v.w * v.w;
#pragma unroll
    for (int off = 16; off; off >>= 1) {
        s += __shfl_xor_sync(0xffffffffu, s, off);
        q += __shfl_xor_sync(0xffffffffu, q, off);
    }
    __shared__ float ss[4], sq[4];
    const int wid = t >> 5, lane = t & 31;
    if (lane == 0) { ss[wid] = s; sq[wid] = q; }
    __syncthreads();
    if (t == 0) {
        float S = ss[0] + ss[1] + ss[2] + ss[3];
        float Q = sq[0] + sq[1] + sq[2] + sq[3];
        float m = S * (1.f / DMQ);
        float var = Q * (1.f / DMQ) - m * m;
        ss[0] = m;
        sq[0] = rsqrtf(var + 1e-5f);
    }
    __syncthreads();
    const float m = ss[0], inv = sq[0];
    float4 wv = ((const float4*)w)[t];
    float4 bv = ((const float4*)b)[t];
    float4 r;
    r.x = (v.x - m) * inv * wv.x + bv.x;
    r.y = (v.y - m) * inv * wv.y + bv.y;
    r.z = (v.z - m) * inv * wv.z + bv.z;
    r.w = (v.w - m) * inv * wv.w + bv.w;
    if (WF32) ((float4*)(o + (size_t)n * DMQ))[t] = r;
    bf162* p16 = (bf162*)(o16 + (size_t)n * DMQ);
    p16[2 * t]     = __floats2bfloat162_rn(r.x, r.y);
    p16[2 * t + 1] = __floats2bfloat162_rn(r.z, r.w);
}

// ---------------- depthwise causal conv (DC=4) + bias + silu ----------------
__global__ void conv_silu_kernel(const bf16* __restrict__ xz,
                                 const float* __restrict__ cw,
                                 const float* __restrict__ cb,
                                 bf16* __restrict__ xs16)
{
    const int idx = blockIdx.x * blockDim.x + threadIdx.x;
    const int d = idx & 1023;
    const int n0 = (idx >> 10) << 2;
    const float4 w = ((const float4*)cw)[d];
    const float bias = cb[d];

    float xm3 = 0.f, xm2 = 0.f, xm1 = 0.f;
    if (n0 > 0) {
        xm3 = __bfloat162float(xz[(size_t)(n0 - 3) * 2048 + d]);
        xm2 = __bfloat162float(xz[(size_t)(n0 - 2) * 2048 + d]);
        xm1 = __bfloat162float(xz[(size_t)(n0 - 1) * 2048 + d]);
    }
    const float x0 = __bfloat162float(xz[(size_t)(n0 + 0) * 2048 + d]);
    const float x1 = __bfloat162float(xz[(size_t)(n0 + 1) * 2048 + d]);
    const float x2 = __bfloat162float(xz[(size_t)(n0 + 2) * 2048 + d]);
    const float x3 = __bfloat162float(xz[(size_t)(n0 + 3) * 2048 + d]);

    float y0 = bias + xm3 * w.x + xm2 * w.y + xm1 * w.z + x0 * w.w;
    float y1 = bias + xm2 * w.x + xm1 * w.y + x0  * w.z + x1 * w.w;
    float y2 = bias + xm1 * w.x + x0  * w.y + x1  * w.z + x2 * w.w;
    float y3 = bias + x0  * w.x + x1  * w.y + x2  * w.z + x3 * w.w;

    y0 = y0 / (1.f + __expf(-y0));
    y1 = y1 / (1.f + __expf(-y1));
    y2 = y2 / (1.f + __expf(-y2));
    y3 = y3 / (1.f + __expf(-y3));

    xs16[(size_t)(n0 + 0) * 1024 + d] = __float2bfloat16_rn(y0);
    xs16[(size_t)(n0 + 1) * 1024 + d] = __float2bfloat16_rn(y1);
    xs16[(size_t)(n0 + 2) * 1024 + d] = __float2bfloat16_rn(y2);
    xs16[(size_t)(n0 + 3) * 1024 + d] = __float2bfloat16_rn(y3);
}

// ---------------- chunked selective scan (bf16 delta/xs inputs) --------------
#define CHN 64
#define DGR 32

template <bool PASS3>
__global__ __launch_bounds__(512) void scan_chunk_kernel(
    const bf16* __restrict__ delta16,
    const bf16* __restrict__ xs16,
    const float* __restrict__ dbc,
    const bf16* __restrict__ xz16,
    const float* __restrict__ Alog,
    const float* __restrict__ Dv,
    const float* __restrict__ Hstart,
    float* __restrict__ Aend,
    float* __restrict__ Hend,
    bf16* __restrict__ y16)
{
    const int chunk = blockIdx.y;
    const int d0 = blockIdx.x * DGR;
    const int n0 = chunk * CHN;
    const int tid = threadIdx.x;
    const int s = tid & 15;
    const int dl = tid >> 4;
    const int d = d0 + dl;

    __shared__ float sh_delta[CHN][DGR];
    __shared__ float sh_xs[CHN][DGR];
    __shared__ float sh_z[CHN][DGR];
    __shared__ float sh_B[CHN][16];
    __shared__ float sh_C[CHN][16];

    for (int i = tid; i < CHN * DGR; i += 512) {
        const int r = i >> 5, c = i & 31;
        sh_delta[r][c] = __bfloat162float(delta16[(size_t)(n0 + r) * DIQ + d0 + c]);
        sh_xs[r][c]    = __bfloat162float(xs16[(size_t)(n0 + r) * DIQ + d0 + c]);
        if (PASS3)
            sh_z[r][c] = __bfloat162float(xz16[(size_t)(n0 + r) * 2048 + DIQ + d0 + c]);
    }
    for (int i = tid; i < CHN * 16; i += 512) {
        const int r = i >> 4, c = i & 15;
        sh_B[r][c] = dbc[(size_t)(n0 + r) * 64 + 32 + c];
        if (PASS3) sh_C[r][c] = dbc[(size_t)(n0 + r) * 64 + 48 + c];
    }
    __syncthreads();

    const float Ads = -expf(Alog[d * DSQ + s]);
    float h = 0.f, aP = 1.f;
    float dv = 0.f;
    if (PASS3) {
        h = Hstart[(size_t)(chunk * DIQ + d) * DSQ + s];
        dv = Dv[d];
    }

#pragma unroll 4
    for (int i = 0; i < CHN; i++) {
        const float dt = sh_delta[i][dl];
        const float xv = sh_xs[i][dl];
        const float a = __expf(dt * Ads);
        h = a * h + dt * sh_B[i][s] * xv;
        if (PASS3) {
            float v = h * sh_C[i][s];
            v += __shfl_xor_sync(0xffffffffu, v, 1);
            v += __shfl_xor_sync(0xffffffffu, v, 2);
            v += __shfl_xor_sync(0xffffffffu, v, 4);
            v += __shfl_xor_sync(0xffffffffu, v, 8);
            if (s == 0) {
                const float yv = v + dv * xv;
                const float zz = sh_z[i][dl];
                const float sig = 1.f / (1.f + __expf(-zz));
                y16[(size_t)(n0 + i) * DIQ + d] = __float2bfloat16_rn(yv * (zz * sig));
            }
        } else {
            aP *= a;
        }
    }
    if (!PASS3) {
        Aend[(size_t)(chunk * DIQ + d) * DSQ + s] = aP;
        Hend[(size_t)(chunk * DIQ + d) * DSQ + s] = h;
    }
}

__global__ void scan_combine_kernel(const float* __restrict__ Aend,
                                    const float* __restrict__ Hend,
                                    float* __restrict__ Hstart)
{
    const int idx = blockIdx.x * blockDim.x + threadIdx.x;
    float h = 0.f;
#pragma unroll 8
    for (int c = 0; c < 64; c++) {
        Hstart[(size_t)c * 16384 + idx] = h;
        h = Aend[(size_t)c * 16384 + idx] * h + Hend[(size_t)c * 16384 + idx];
    }
}

// ---------------- attention head --------------------------------------------
__global__ void asc_kernel(const float* __restrict__ k,
                           const float* __restrict__ w2,
                           const float* __restrict__ b2,
                           float* __restrict__ asc)
{
    const int gw = (blockIdx.x * blockDim.x + threadIdx.x) >> 5;
    const int lane = threadIdx.x & 31;
    const float4 a = ((const float4*)(k + (size_t)gw * 128))[lane];
    const float4 w = ((const float4*)w2)[lane];
    float s = a.x * w.x + a.y * w.y + a.z * w.z + a.w * w.w;
#pragma unroll
    for (int off = 16; off; off >>= 1) s += __shfl_xor_sync(0xffffffffu, s, off);
    if (lane == 0) asc[gw] = s + b2[0];
}

__global__ void softmax_kernel(const float* __restrict__ asc,
                               float* __restrict__ wts,
                               float* __restrict__ out)
{
    __shared__ float red[32];
    __shared__ float bc;
    const int t = threadIdx.x;
    const float4 v = ((const float4*)asc)[t];
    float mx = fmaxf(fmaxf(v.x, v.y), fmaxf(v.z, v.w));
#pragma unroll
    for (int off = 16; off; off >>= 1) mx = fmaxf(mx, __shfl_xor_sync(0xffffffffu, mx, off));
    if ((t & 31) == 0) red[t >> 5] = mx;
    __syncthreads();
    if (t < 32) {
        float m = red[t];
#pragma unroll
        for (int off = 16; off; off >>= 1) m = fmaxf(m, __shfl_xor_sync(0xffffffffu, m, off));
        if (t == 0) bc = m;
    }
    __syncthreads();
    const float M = bc;
    float e0 = __expf(v.x - M), e1 = __expf(v.y - M);
    float e2 = __expf(v.z - M), e3 = __expf(v.w - M);
    float s = e0 + e1 + e2 + e3;
#pragma unroll
    for (int off = 16; off; off >>= 1) s += __shfl_xor_sync(0xffffffffu, s, off);
    __syncthreads();
    if ((t & 31) == 0) red[t >> 5] = s;
    __syncthreads();
    if (t < 32) {
        float m = red[t];
#pragma unroll
        for (int off = 16; off; off >>= 1) m += __shfl_xor_sync(0xffffffffu, m, off);
        if (t == 0) bc = m;
    }
    __syncthreads();
    const float inv = 1.f / bc;
    e0 *= inv; e1 *= inv; e2 *= inv; e3 *= inv;
    ((float4*)wts)[t] = make_float4(e0, e1, e2, e3);
    out[2 + 4 * t + 0] = e0;
    out[2 + 4 * t + 1] = e1;
    out[2 + 4 * t + 2] = e2;
    out[2 + 4 * t + 3] = e3;
}

__global__ void pooled_kernel(const float* __restrict__ hf,
                              const float* __restrict__ wts,
                              float* __restrict__ pooled)
{
    const int d = threadIdx.x;
    const int n0 = blockIdx.x * 256;
    float acc = 0.f;
#pragma unroll 4
    for (int i = 0; i < 256; i++)
        acc += wts[n0 + i] * hf[(size_t)(n0 + i) * DMQ + d];
    atomicAdd(&pooled[d], acc);
}

__global__ void classifier_kernel(const float* __restrict__ pooled,
                                  const float* __restrict__ cw,
                                  const float* __restrict__ cb,
                                  float* __restrict__ out)
{
    const int lane = threadIdx.x;
    float s0 = 0.f, s1 = 0.f;
    for (int d = lane; d < DMQ; d += 32) {
        const float p = pooled[d];
        s0 += p * cw[d];
        s1 += p * cw[DMQ + d];
    }
#pragma unroll
    for (int off = 16; off; off >>= 1) {
        s0 += __shfl_xor_sync(0xffffffffu, s0, off);
        s1 += __shfl_xor_sync(0xffffffffu, s1, off);
    }
    if (lane == 0) {
        const float l0 = s0 + cb[0], l1 = s1 + cb[1];
        out[0] = 1.f / (1.f + expf(-l0));
        out[1] = 1.f / (1.f + expf(-l1));
        const float m = fmaxf(l0, l1);
        const float e0 = expf(l0 - m), e1 = expf(l1 - m);
        const float inv = 1.f / (e0 + e1);
        out[2 + NTOK] = e0 * inv;
        out[3 + NTOK] = e1 * inv;
        out[4 + NTOK] = (l1 > l0) ? 1.f : 0.f;
    }
}

// ---------------- orchestration ---------------------------------------------
static const int SMEM_N128_S4 = 4 * (128 + 128) * RSB;  // 81920
static const int SMEM_N128_S8 = 8 * (128 + 128) * RSB;  // 163840
static const int SMEM_N64_S4  = 4 * (128 + 64) * RSB;   // 61440
static const int SMEM_N64_S8  = 8 * (128 + 64) * RSB;   // 122880

extern "C" void kernel_launch(void* const* d_in, const int* in_sizes, int n_in,
                              void* d_out, int out_size)
{
    const float* x     = (const float*)d_in[0];
    const float* fc1_w = (const float*)d_in[1];
    const float* fc1_b = (const float*)d_in[2];
    const float* ln_w  = (const float*)d_in[3];
    const float* ln_b  = (const float*)d_in[4];
    const float* ipw   = (const float*)d_in[5];
    const float* cw    = (const float*)d_in[6];
    const float* cb    = (const float*)d_in[7];
    const float* xpw   = (const float*)d_in[8];
    const float* dtw   = (const float*)d_in[9];
    const float* dtb   = (const float*)d_in[10];
    const float* Alog  = (const float*)d_in[11];
    const float* Dv    = (const float*)d_in[12];
    const float* opw   = (const float*)d_in[13];
    const float* nw    = (const float*)d_in[14];
    const float* nb    = (const float*)d_in[15];
    const float* aw1   = (const float*)d_in[16];
    const float* ab1   = (const float*)d_in[17];
    const float* aw2   = (const float*)d_in[18];
    const float* ab2   = (const float*)d_in[19];
    const float* cwc   = (const float*)d_in[20];
    const float* cbc   = (const float*)d_in[21];
    float* out = (float*)d_out;

    float *p_h, *p_ln, *p_dbc, *p_dbcp;
    float *p_Aend, *p_Hend, *p_Hstart, *p_k, *p_asc, *p_wts, *p_pooled;
    bf16 *p_x16, *p_ln16, *p_xz16, *p_xs16, *p_dbc16, *p_delta16, *p_y16;
    bf16 *p_fc1w16, *p_ipw16, *p_xpw16, *p_dtw16, *p_opw16, *p_aw116;
    cudaGetSymbolAddress((void**)&p_h, g_h);
    cudaGetSymbolAddress((void**)&p_ln, g_ln);
    cudaGetSymbolAddress((void**)&p_dbc, g_dbc);
    cudaGetSymbolAddress((void**)&p_dbcp, g_dbcp);
    cudaGetSymbolAddress((void**)&p_Aend, g_Aend);
    cudaGetSymbolAddress((void**)&p_Hend, g_Hend);
    cudaGetSymbolAddress((void**)&p_Hstart, g_Hstart);
    cudaGetSymbolAddress((void**)&p_k, g_attnk);
    cudaGetSymbolAddress((void**)&p_asc, g_asc);
    cudaGetSymbolAddress((void**)&p_wts, g_wts);
    cudaGetSymbolAddress((void**)&p_pooled, g_pooled);
    cudaGetSymbolAddress((void**)&p_x16, g_x16);
    cudaGetSymbolAddress((void**)&p_ln16, g_ln16);
    cudaGetSymbolAddress((void**)&p_xz16, g_xz16);
    cudaGetSymbolAddress((void**)&p_xs16, g_xs16);
    cudaGetSymbolAddress((void**)&p_dbc16, g_dbc16);
    cudaGetSymbolAddress((void**)&p_delta16, g_delta16);
    cudaGetSymbolAddress((void**)&p_y16, g_y16);
    cudaGetSymbolAddress((void**)&p_fc1w16, g_fc1w16);
    cudaGetSymbolAddress((void**)&p_ipw16, g_ipw16);
    cudaGetSymbolAddress((void**)&p_xpw16, g_xpw16);
    cudaGetSymbolAddress((void**)&p_dtw16, g_dtw16);
    cudaGetSymbolAddress((void**)&p_opw16, g_opw16);
    cudaGetSymbolAddress((void**)&p_aw116, g_aw116);

    cudaFuncSetAttribute(gemm16_kernel<1, 128, 8, false, true,  false>, cudaFuncAttributeMaxDynamicSharedMemorySize, SMEM_N128_S8);
    cudaFuncSetAttribute(gemm16_kernel<3, 128, 8, false, true,  false>, cudaFuncAttributeMaxDynamicSharedMemorySize, SMEM_N128_S8);
    cudaFuncSetAttribute(gemm16_kernel<4, 64,  8, false, true,  false>, cudaFuncAttributeMaxDynamicSharedMemorySize, SMEM_N64_S8);
    cudaFuncSetAttribute(gemm16_kernel<0, 128, 4, true,  false, false>, cudaFuncAttributeMaxDynamicSharedMemorySize, SMEM_N128_S4);
    cudaFuncSetAttribute(gemm16_kernel<2, 128, 4, true,  false, false>, cudaFuncAttributeMaxDynamicSharedMemorySize, SMEM_N128_S4);
    cudaFuncSetAttribute(gemm16_kernel<0, 64,  4, false, true,  true >, cudaFuncAttributeMaxDynamicSharedMemorySize, SMEM_N64_S4);

    // converts (3 launches)
    {
        int n0 = NTOK * F0Q / 4;
        cvt3_kernel<<<(n0 + 255) / 256, 256>>>(x, p_x16, n0,
                                               (const float*)0, (bf16*)0, 0,
                                               (const float*)0, (bf16*)0, 0);
        int a = DMQ * F0Q / 4, b = NLQ * 2 * DIQ * DMQ / 4, c = NLQ * DMQ * DIQ / 4;
        cvt3_kernel<<<(a + b + c + 255) / 256, 256>>>(fc1_w, p_fc1w16, a,
                                                      ipw, p_ipw16, b,
                                                      opw, p_opw16, c);
        int d = NLQ * 64 * DIQ / 4, e = NLQ * DIQ * DTRQ / 4, f = 128 * DMQ / 4;
        cvt3_kernel<<<(d + e + f + 255) / 256, 256>>>(xpw, p_xpw16, d,
                                                      dtw, p_dtw16, e,
                                                      aw1, p_aw116, f);
    }

    // h = relu(x @ fc1_w^T + fc1_b)   (8-stage, batched fragments)
    gemm16_kernel<1, 128, 8, false, true, false><<<dim3(DMQ / 128, NTOK / 128), 256, SMEM_N128_S8>>>(
        p_x16, F0Q, p_fc1w16, F0Q, p_h, DMQ, (bf16*)0, fc1_b, 0, F0Q);

    for (int l = 0; l < NLQ; l++) {
        layernorm_kernel<false><<<NTOK, 128>>>(p_h, ln_w + l * DMQ, ln_b + l * DMQ,
                                               (float*)0, p_ln16);

        // xz = h_ln @ ipw^T  (bf16-only; 4-stage, grid 512)
        gemm16_kernel<0, 128, 4, true, false, false><<<dim3(2 * DIQ / 128, NTOK / 128), 256, SMEM_N128_S4>>>(
            p_ln16, DMQ, p_ipw16 + (size_t)l * 2 * DIQ * DMQ, DMQ, (float*)0, 2 * DIQ,
            p_xz16, (const float*)0, 0, DMQ);

        // xs = silu(conv(xin) + cb)  (bf16-only)
        conv_silu_kernel<<<NTOK * DIQ / 4 / 256, 256>>>(
            p_xz16, cw + l * DIQ * DCQ, cb + l * DIQ, p_xs16);

        // dbc = xs @ xpw^T via split-K x8
        gemm16_kernel<0, 64, 4, false, true, true><<<dim3(1, NTOK / 128, KSPLIT), 256, SMEM_N64_S4>>>(
            p_xs16, DIQ, p_xpw16 + (size_t)l * 64 * DIQ, DIQ, p_dbcp, 64,
            (bf16*)0, (const float*)0, NTOK * 64, DIQ / KSPLIT);
        dbc_reduce_kernel<<<NTOK * 64 / 4 / 256, 256>>>(p_dbcp, p_dbc, p_dbc16);

        // delta = softplus(dt @ dtw^T + dtb)  (bf16-only output)
        gemm16_kernel<2, 128, 4, true, false, false><<<dim3(DIQ / 128, NTOK / 128), 256, SMEM_N128_S4>>>(
            p_dbc16, 64, p_dtw16 + (size_t)l * DIQ * DTRQ, DTRQ, (float*)0, DIQ,
            p_delta16, dtb + l * DIQ, 0, DTRQ);

        // chunked selective scan (bf16 delta/xs)
        scan_chunk_kernel<false><<<dim3(DIQ / DGR, 64), 512>>>(
            p_delta16, p_xs16, p_dbc, (const bf16*)0,
            Alog + (size_t)l * DIQ * DSQ, (const float*)0, (const float*)0,
            p_Aend, p_Hend, (bf16*)0);
        scan_combine_kernel<<<DIQ * DSQ / 256, 256>>>(p_Aend, p_Hend, p_Hstart);
        scan_chunk_kernel<true><<<dim3(DIQ / DGR, 64), 512>>>(
            p_delta16, p_xs16, p_dbc, p_xz16,
            Alog + (size_t)l * DIQ * DSQ, Dv + l * DIQ, p_Hstart,
            (float*)0, (float*)0, p_y16);

        // h = h + y @ opw^T   (8-stage, batched fragments)
        gemm16_kernel<3, 128, 8, false, true, false><<<dim3(DMQ / 128, NTOK / 128), 256, SMEM_N128_S8>>>(
            p_y16, DIQ, p_opw16 + (size_t)l * DMQ * DIQ, DIQ, p_h, DMQ,
            (bf16*)0, p_h, DMQ, DIQ);
    }

    layernorm_kernel<true><<<NTOK, 128>>>(p_h, nw, nb, p_ln, p_ln16);

    // k = tanh(h_f @ aw1^T + ab1)   (8-stage, batched fragments)
    gemm16_kernel<4, 64, 8, false, true, false><<<dim3(2, NTOK / 128), 256, SMEM_N64_S8>>>(
        p_ln16, DMQ, p_aw116, DMQ, p_k, 128, (bf16*)0, ab1, 0, DMQ);

    asc_kernel<<<NTOK / 32, 1024>>>(p_k, aw2, ab2, p_asc);
    softmax_kernel<<<1, 1024>>>(p_asc, p_wts, out);

    cudaMemsetAsync(p_pooled, 0, DMQ * sizeof(float));
    pooled_kernel<<<16, 512>>>(p_ln, p_wts, p_pooled);
    classifier_kernel<<<1, 32>>>(p_pooled, cwc, cbc, out);
}

// round 17
// speedup vs baseline: 1.0626x; 1.0074x over previous
#include <cuda_runtime.h>
#include <cuda_bf16.h>
#include <math.h>
#include <stdint.h>

#define DMQ 512
#define DIQ 1024
#define DSQ 16
#define DCQ 4
#define DTRQ 32
#define NLQ 2
#define NTOK 4096
#define F0Q 1024
#define KSPLIT 8

typedef __nv_bfloat16 bf16;
typedef __nv_bfloat162 bf162;

// ---------------- scratch (device globals: allocation-free) ----------------
__device__ float g_h[NTOK * DMQ];
__device__ float g_ln[NTOK * DMQ];
__device__ float g_dbc[NTOK * 64];
__device__ float g_dbcp[KSPLIT * NTOK * 64];
__device__ float g_Aend[64 * DIQ * DSQ];
__device__ float g_Hend[64 * DIQ * DSQ];
__device__ float g_Hstart[64 * DIQ * DSQ];
__device__ float g_attnk[NTOK * 128];
__device__ float g_asc[NTOK];
__device__ float g_wts[NTOK];
__device__ float g_pooled[DMQ];
// bf16 buffers
__device__ bf16 g_x16[NTOK * F0Q];
__device__ bf16 g_ln16[NTOK * DMQ];
__device__ bf16 g_xz16[NTOK * 2 * DIQ];
__device__ bf16 g_xs16[NTOK * DIQ];
__device__ bf16 g_dbc16[NTOK * 64];
__device__ bf16 g_delta16[NTOK * DIQ];
__device__ bf16 g_y16[NTOK * DIQ];
__device__ bf16 g_fc1w16[DMQ * F0Q];
__device__ bf16 g_ipw16[NLQ * 2 * DIQ * DMQ];
__device__ bf16 g_xpw16[NLQ * 64 * DIQ];
__device__ bf16 g_dtw16[NLQ * DIQ * DTRQ];
__device__ bf16 g_opw16[NLQ * DMQ * DIQ];
__device__ bf16 g_aw116[128 * DMQ];

// ---------------- PTX helpers ------------------------------------------------
__device__ __forceinline__ uint32_t smem_u32(const void* p) {
    uint32_t a;
    asm("{ .reg .u64 t; cvta.to.shared.u64 t, %1; cvt.u32.u64 %0, t; }"
        : "=r"(a) : "l"(p));
    return a;
}

__device__ __forceinline__ void cp_async16(uint32_t dst, const void* src) {
    asm volatile("cp.async.ca.shared.global [%0], [%1], 16;"
                 :: "r"(dst), "l"(src) : "memory");
}
__device__ __forceinline__ void cp_commit() {
    asm volatile("cp.async.commit_group;" ::: "memory");
}
template <int N>
__device__ __forceinline__ void cp_wait() {
    asm volatile("cp.async.wait_group %0;" :: "n"(N) : "memory");
}

__device__ __forceinline__ void ldsm4(uint32_t* r, uint32_t addr) {
    asm volatile("ldmatrix.sync.aligned.m8n8.x4.shared.b16 {%0,%1,%2,%3}, [%4];"
                 : "=r"(r[0]), "=r"(r[1]), "=r"(r[2]), "=r"(r[3]) : "r"(addr));
}

__device__ __forceinline__ void mma_bf16(float* d, const uint32_t* a, const uint32_t* b) {
    asm volatile(
        "mma.sync.aligned.m16n8k16.row.col.f32.bf16.bf16.f32 "
        "{%0,%1,%2,%3}, {%4,%5,%6,%7}, {%8,%9}, {%0,%1,%2,%3};\n"
        : "+f"(d[0]), "+f"(d[1]), "+f"(d[2]), "+f"(d[3])
        : "r"(a[0]), "r"(a[1]), "r"(a[2]), "r"(a[3]), "r"(b[0]), "r"(b[1]));
}

// ---------------- fp32 -> bf16 convert (up to 3 regions per launch) ----------
__global__ void cvt3_kernel(const float* __restrict__ s0, bf16* __restrict__ d0, int n0,
                            const float* __restrict__ s1, bf16* __restrict__ d1, int n1,
                            const float* __restrict__ s2, bf16* __restrict__ d2, int n2)
{
    int i = blockIdx.x * blockDim.x + threadIdx.x;
    const float* s; bf16* d; int j;
    if (i < n0)               { s = s0; d = d0; j = i; }
    else if (i < n0 + n1)     { s = s1; d = d1; j = i - n0; }
    else if (i < n0 + n1 + n2){ s = s2; d = d2; j = i - n0 - n1; }
    else return;
    const float4 v = ((const float4*)s)[j];
    bf162* o = (bf162*)d;
    o[2 * j]     = __floats2bfloat162_rn(v.x, v.y);
    o[2 * j + 1] = __floats2bfloat162_rn(v.z, v.w);
}

// ---------------- bf16 tensor-core GEMM -------------------------------------
// C = A[M,K] * B[N,K]^T, bf16 row-major. CTA 128 x NT.
// STAGES<=4: 256 threads (8 warps), 2 CTAs/SM.
// STAGES>4:  512 threads (16 warps), 1 CTA/SM (deep ring, grid-starved GEMMs).
// BK=32, cp.async ring, rows padded to 80 B.
// EPI: 0 none, 1 bias+relu, 2 bias+softplus, 3 residual add, 4 bias+tanh
// SPLITK: grid.z = K-slice; fp32 partials at C + z*ldaux.
#define RSB 80

template <int EPI, int NT, int STAGES, bool WB16, bool WF32, bool SPLITK>
__global__ __launch_bounds__((STAGES > 4 ? 512 : 256), (STAGES > 4 ? 1 : 2))
void gemm16_kernel(
    const bf16* __restrict__ A, int lda,
    const bf16* __restrict__ B, int ldb,
    float* __restrict__ C, int ldc,
    bf16* __restrict__ C16,
    const float* __restrict__ aux, int ldaux,
    int K)
{
    constexpr int BLK = (STAGES > 4) ? 512 : 256;
    constexpr int NW = BLK / 32;
    constexpr int WN = NT / 32;
    constexpr int WM = NW / WN;
    constexpr int MI = 128 / (WM * 16);
    constexpr int NI = 4;
    constexpr int ASTG = 128 * RSB;
    constexpr int BSTG = NT * RSB;
    constexpr int STGB = ASTG + BSTG;

    extern __shared__ char smraw[];
    const uint32_t sbase = smem_u32(smraw);

    const int tid = threadIdx.x;
    const int wid = tid >> 5;
    const int lane = tid & 31;
    const int fr = lane >> 2;
    const int fc = lane & 3;
    const int wm = (wid % WM) * (MI * 16);
    const int wn = (wid / WM) * 32;
    const int bm = blockIdx.y * 128;
    const int bn = blockIdx.x * NT;

    if (SPLITK) {
        A += (size_t)blockIdx.z * K;
        B += (size_t)blockIdx.z * K;
    }

    float acc[MI][NI][4];
#pragma unroll
    for (int mi = 0; mi < MI; mi++)
#pragma unroll
        for (int ni = 0; ni < NI; ni++)
#pragma unroll
            for (int j = 0; j < 4; j++) acc[mi][ni][j] = 0.f;

    auto load_stage = [&](int stg, int c) {
        const int k0 = c << 5;
        const uint32_t abuf = sbase + stg * STGB;
        const uint32_t bbuf = abuf + ASTG;
#pragma unroll
        for (int u = tid; u < 128 * 4; u += BLK) {
            const int r = u >> 2, q = u & 3;
            cp_async16(abuf + r * RSB + q * 16,
                       A + (size_t)(bm + r) * lda + k0 + q * 8);
        }
#pragma unroll
        for (int u = tid; u < NT * 4; u += BLK) {
            const int r = u >> 2, q = u & 3;
            cp_async16(bbuf + r * RSB + q * 16,
                       B + (size_t)(bn + r) * ldb + k0 + q * 8);
        }
    };

    const int nch = K >> 5;
#pragma unroll
    for (int i = 0; i < STAGES - 1; i++) {
        if (i < nch) load_stage(i, i);
        cp_commit();
    }

    const int a_r = lane & 15, a_c8 = (lane >> 4) << 3;
    const int b_r = (lane & 7) + ((lane >> 4) << 3), b_c8 = lane & 8;

    for (int c = 0; c < nch; c++) {
        const int stg = c % STAGES;
        cp_wait<STAGES - 2>();
        __syncthreads();

        if (c + STAGES - 1 < nch) load_stage((c + STAGES - 1) % STAGES, c + STAGES - 1);
        cp_commit();

        const uint32_t abuf = sbase + stg * STGB;
        const uint32_t bbuf = abuf + ASTG;
#pragma unroll
        for (int kk = 0; kk < 2; kk++) {
            const int kb = kk << 4;
            uint32_t afr[MI][4], bfr[NI][2];
#pragma unroll
            for (int mi = 0; mi < MI; mi++)
                ldsm4(afr[mi],
                      abuf + (wm + mi * 16 + a_r) * RSB + (kb + a_c8) * 2);
#pragma unroll
            for (int n2 = 0; n2 < NI / 2; n2++) {
                uint32_t r4[4];
                ldsm4(r4, bbuf + (wn + n2 * 16 + b_r) * RSB + (kb + b_c8) * 2);
                bfr[2 * n2][0] = r4[0]; bfr[2 * n2][1] = r4[1];
                bfr[2 * n2 + 1][0] = r4[2]; bfr[2 * n2 + 1][1] = r4[3];
            }
#pragma unroll
            for (int mi = 0; mi < MI; mi++)
#pragma unroll
                for (int ni = 0; ni < NI; ni++)
                    mma_bf16(acc[mi][ni], afr[mi], bfr[ni]);
        }
    }

    float* Cw = C;
    if (SPLITK) Cw = C + (size_t)blockIdx.z * ldaux;

#pragma unroll
    for (int mi = 0; mi < MI; mi++) {
#pragma unroll
        for (int ni = 0; ni < NI; ni++) {
#pragma unroll
            for (int half = 0; half < 2; half++) {
                const int m = bm + wm + mi * 16 + fr + (half << 3);
                const int n = bn + wn + ni * 8 + (fc << 1);
                float v0 = acc[mi][ni][half * 2 + 0];
                float v1 = acc[mi][ni][half * 2 + 1];
                if (EPI == 1) {
                    v0 = fmaxf(v0 + aux[n], 0.f);
                    v1 = fmaxf(v1 + aux[n + 1], 0.f);
                } else if (EPI == 2) {
                    v0 += aux[n]; v1 += aux[n + 1];
                    v0 = (v0 > 20.f) ? v0 : log1pf(expf(v0));
                    v1 = (v1 > 20.f) ? v1 : log1pf(expf(v1));
                } else if (EPI == 3) {
                    const float2 r = *(const float2*)(aux + (size_t)m * ldaux + n);
                    v0 += r.x; v1 += r.y;
                } else if (EPI == 4) {
                    v0 = tanhf(v0 + aux[n]);
                    v1 = tanhf(v1 + aux[n + 1]);
                }
                if (SPLITK || WF32) {
                    float2 o; o.x = v0; o.y = v1;
                    *(float2*)(Cw + (size_t)m * ldc + n) = o;
                }
                if (!SPLITK && WB16)
                    *(bf162*)(C16 + (size_t)m * ldc + n) = __floats2bfloat162_rn(v0, v1);
            }
        }
    }
}

// ---------------- split-K reduce for dbc ------------------------------------
__global__ void dbc_reduce_kernel(const float* __restrict__ part,
                                  float* __restrict__ dbc,
                                  bf16* __restrict__ dbc16)
{
    const int i = blockIdx.x * blockDim.x + threadIdx.x;
    float4 s = ((const float4*)part)[i];
#pragma unroll
    for (int k = 1; k < KSPLIT; k++) {
        const float4 v = ((const float4*)(part + (size_t)k * NTOK * 64))[i];
        s.x += v.x; s.y += v.y; s.z += v.z; s.w += v.w;
    }
    ((float4*)dbc)[i] = s;
    bf162* o = (bf162*)dbc16;
    o[2 * i]     = __floats2bfloat162_rn(s.x, s.y);
    o[2 * i + 1] = __floats2bfloat162_rn(s.z, s.w);
}

// ---------------- layernorm (512) ------------------------------------------
template <bool WF32>
__global__ void layernorm_kernel(const float* __restrict__ x,
                                 const float* __restrict__ w,
                                 const float* __restrict__ b,
                                 float* __restrict__ o,
                                 bf16* __restrict__ o16)
{
    const int n = blockIdx.x;
    const int t = threadIdx.x;
    float4 v = ((const float4*)(x + (size_t)n * DMQ))[t];
    float s = v.x + v.y + v.z + v.w;
    float q = v.x * v.x + v.y * v.y + v.z * v.z + v.w * v.w;
#pragma unroll
    for (int off = 16; off; off >>= 1) {
        s += __shfl_xor_sync(0xffffffffu, s, off);
        q += __shfl_xor_sync(0xffffffffu, q, off);
    }
    __shared__ float ss[4], sq[4];
    const int wid = t >> 5, lane = t & 31;
    if (lane == 0) { ss[wid] = s; sq[wid] = q; }
    __syncthreads();
    if (t == 0) {
        float S = ss[0] + ss[1] + ss[2] + ss[3];
        float Q = sq[0] + sq[1] + sq[2] + sq[3];
        float m = S * (1.f / DMQ);
        float var = Q * (1.f / DMQ) - m * m;
        ss[0] = m;
        sq[0] = rsqrtf(var + 1e-5f);
    }
    __syncthreads();
    const float m = ss[0], inv = sq[0];
    float4 wv = ((const float4*)w)[t];
    float4 bv = ((const float4*)b)[t];
    float4 r;
    r.x = (v.x - m) * inv * wv.x + bv.x;
    r.y = (v.y - m) * inv * wv.y + bv.y;
    r.z = (v.z - m) * inv * wv.z + bv.z;
    r.w = (v.w - m) * inv * wv.w + bv.w;
    if (WF32) ((float4*)(o + (size_t)n * DMQ))[t] = r;
    bf162* p16 = (bf162*)(o16 + (size_t)n * DMQ);
    p16[2 * t]     = __floats2bfloat162_rn(r.x, r.y);
    p16[2 * t + 1] = __floats2bfloat162_rn(r.z, r.w);
}

// ---------------- depthwise causal conv (DC=4) + bias + silu ----------------
__global__ void conv_silu_kernel(const bf16* __restrict__ xz,
                                 const float* __restrict__ cw,
                                 const float* __restrict__ cb,
                                 bf16* __restrict__ xs16)
{
    const int idx = blockIdx.x * blockDim.x + threadIdx.x;
    const int d = idx & 1023;
    const int n0 = (idx >> 10) << 2;
    const float4 w = ((const float4*)cw)[d];
    const float bias = cb[d];

    float xm3 = 0.f, xm2 = 0.f, xm1 = 0.f;
    if (n0 > 0) {
        xm3 = __bfloat162float(xz[(size_t)(n0 - 3) * 2048 + d]);
        xm2 = __bfloat162float(xz[(size_t)(n0 - 2) * 2048 + d]);
        xm1 = __bfloat162float(xz[(size_t)(n0 - 1) * 2048 + d]);
    }
    const float x0 = __bfloat162float(xz[(size_t)(n0 + 0) * 2048 + d]);
    const float x1 = __bfloat162float(xz[(size_t)(n0 + 1) * 2048 + d]);
    const float x2 = __bfloat162float(xz[(size_t)(n0 + 2) * 2048 + d]);
    const float x3 = __bfloat162float(xz[(size_t)(n0 + 3) * 2048 + d]);

    float y0 = bias + xm3 * w.x + xm2 * w.y + xm1 * w.z + x0 * w.w;
    float y1 = bias + xm2 * w.x + xm1 * w.y + x0  * w.z + x1 * w.w;
    float y2 = bias + xm1 * w.x + x0  * w.y + x1  * w.z + x2 * w.w;
    float y3 = bias + x0  * w.x + x1  * w.y + x2  * w.z + x3 * w.w;

    y0 = y0 / (1.f + __expf(-y0));
    y1 = y1 / (1.f + __expf(-y1));
    y2 = y2 / (1.f + __expf(-y2));
    y3 = y3 / (1.f + __expf(-y3));

    xs16[(size_t)(n0 + 0) * 1024 + d] = __float2bfloat16_rn(y0);
    xs16[(size_t)(n0 + 1) * 1024 + d] = __float2bfloat16_rn(y1);
    xs16[(size_t)(n0 + 2) * 1024 + d] = __float2bfloat16_rn(y2);
    xs16[(size_t)(n0 + 3) * 1024 + d] = __float2bfloat16_rn(y3);
}

// ---------------- chunked selective scan (bf16 inputs, vectorized loads) -----
#define CHN 64
#define DGR 32

template <bool PASS3>
__global__ __launch_bounds__(512) void scan_chunk_kernel(
    const bf16* __restrict__ delta16,
    const bf16* __restrict__ xs16,
    const float* __restrict__ dbc,
    const bf16* __restrict__ xz16,
    const float* __restrict__ Alog,
    const float* __restrict__ Dv,
    const float* __restrict__ Hstart,
    float* __restrict__ Aend,
    float* __restrict__ Hend,
    bf16* __restrict__ y16)
{
    const int chunk = blockIdx.y;
    const int d0 = blockIdx.x * DGR;
    const int n0 = chunk * CHN;
    const int tid = threadIdx.x;
    const int s = tid & 15;
    const int dl = tid >> 4;
    const int d = d0 + dl;

    __shared__ float sh_delta[CHN][DGR];
    __shared__ float sh_xs[CHN][DGR];
    __shared__ float sh_z[CHN][DGR];
    __shared__ float sh_B[CHN][16];
    __shared__ float sh_C[CHN][16];

    // vectorized staging: 16 bf162 per row of 32
    for (int i = tid; i < CHN * (DGR / 2); i += 512) {
        const int r = i >> 4, c2 = (i & 15) << 1;
        float2 vd = __bfloat1622float2(
            *(const bf162*)(delta16 + (size_t)(n0 + r) * DIQ + d0 + c2));
        sh_delta[r][c2] = vd.x; sh_delta[r][c2 + 1] = vd.y;
        float2 vx = __bfloat1622float2(
            *(const bf162*)(xs16 + (size_t)(n0 + r) * DIQ + d0 + c2));
        sh_xs[r][c2] = vx.x; sh_xs[r][c2 + 1] = vx.y;
        if (PASS3) {
            float2 vz = __bfloat1622float2(
                *(const bf162*)(xz16 + (size_t)(n0 + r) * 2048 + DIQ + d0 + c2));
            sh_z[r][c2] = vz.x; sh_z[r][c2 + 1] = vz.y;
        }
    }
    for (int i = tid; i < CHN * 8; i += 512) {
        const int r = i >> 3, c2 = (i & 7) << 1;
        const float2 vb = *(const float2*)(dbc + (size_t)(n0 + r) * 64 + 32 + c2);
        sh_B[r][c2] = vb.x; sh_B[r][c2 + 1] = vb.y;
        if (PASS3) {
            const float2 vc = *(const float2*)(dbc + (size_t)(n0 + r) * 64 + 48 + c2);
            sh_C[r][c2] = vc.x; sh_C[r][c2 + 1] = vc.y;
        }
    }
    __syncthreads();

    const float Ads = -expf(Alog[d * DSQ + s]);
    float h = 0.f, aP = 1.f;
    float dv = 0.f;
    if (PASS3) {
        h = Hstart[(size_t)(chunk * DIQ + d) * DSQ + s];
        dv = Dv[d];
    }

#pragma unroll 4
    for (int i = 0; i < CHN; i++) {
        const float dt = sh_delta[i][dl];
        const float xv = sh_xs[i][dl];
        const float a = __expf(dt * Ads);
        h = a * h + dt * sh_B[i][s] * xv;
        if (PASS3) {
            float v = h * sh_C[i][s];
            v += __shfl_xor_sync(0xffffffffu, v, 1);
            v += __shfl_xor_sync(0xffffffffu, v, 2);
            v += __shfl_xor_sync(0xffffffffu, v, 4);
            v += __shfl_xor_sync(0xffffffffu, v, 8);
            if (s == 0) {
                const float yv = v + dv * xv;
                const float zz = sh_z[i][dl];
                const float sig = 1.f / (1.f + __expf(-zz));
                y16[(size_t)(n0 + i) * DIQ + d] = __float2bfloat16_rn(yv * (zz * sig));
            }
        } else {
            aP *= a;
        }
    }
    if (!PASS3) {
        Aend[(size_t)(chunk * DIQ + d) * DSQ + s] = aP;
        Hend[(size_t)(chunk * DIQ + d) * DSQ + s] = h;
    }
}

__global__ void scan_combine_kernel(const float* __restrict__ Aend,
                                    const float* __restrict__ Hend,
                                    float* __restrict__ Hstart)
{
    const int idx = blockIdx.x * blockDim.x + threadIdx.x;
    float h = 0.f;
#pragma unroll 8
    for (int c = 0; c < 64; c++) {
        Hstart[(size_t)c * 16384 + idx] = h;
        h = Aend[(size_t)c * 16384 + idx] * h + Hend[(size_t)c * 16384 + idx];
    }
}

// ---------------- attention head --------------------------------------------
__global__ void asc_kernel(const float* __restrict__ k,
                           const float* __restrict__ w2,
                           const float* __restrict__ b2,
                           float* __restrict__ asc)
{
    const int gw = (blockIdx.x * blockDim.x + threadIdx.x) >> 5;
    const int lane = threadIdx.x & 31;
    const float4 a = ((const float4*)(k + (size_t)gw * 128))[lane];
    const float4 w = ((const float4*)w2)[lane];
    float s = a.x * w.x + a.y * w.y + a.z * w.z + a.w * w.w;
#pragma unroll
    for (int off = 16; off; off >>= 1) s += __shfl_xor_sync(0xffffffffu, s, off);
    if (lane == 0) asc[gw] = s + b2[0];
}

__global__ void softmax_kernel(const float* __restrict__ asc,
                               float* __restrict__ wts,
                               float* __restrict__ out)
{
    __shared__ float red[32];
    __shared__ float bc;
    const int t = threadIdx.x;
    const float4 v = ((const float4*)asc)[t];
    float mx = fmaxf(fmaxf(v.x, v.y), fmaxf(v.z, v.w));
#pragma unroll
    for (int off = 16; off; off >>= 1) mx = fmaxf(mx, __shfl_xor_sync(0xffffffffu, mx, off));
    if ((t & 31) == 0) red[t >> 5] = mx;
    __syncthreads();
    if (t < 32) {
        float m = red[t];
#pragma unroll
        for (int off = 16; off; off >>= 1) m = fmaxf(m, __shfl_xor_sync(0xffffffffu, m, off));
        if (t == 0) bc = m;
    }
    __syncthreads();
    const float M = bc;
    float e0 = __expf(v.x - M), e1 = __expf(v.y - M);
    float e2 = __expf(v.z - M), e3 = __expf(v.w - M);
    float s = e0 + e1 + e2 + e3;
#pragma unroll
    for (int off = 16; off; off >>= 1) s += __shfl_xor_sync(0xffffffffu, s, off);
    __syncthreads();
    if ((t & 31) == 0) red[t >> 5] = s;
    __syncthreads();
    if (t < 32) {
        float m = red[t];
#pragma unroll
        for (int off = 16; off; off >>= 1) m += __shfl_xor_sync(0xffffffffu, m, off);
        if (t == 0) bc = m;
    }
    __syncthreads();
    const float inv = 1.f / bc;
    e0 *= inv; e1 *= inv; e2 *= inv; e3 *= inv;
    ((float4*)wts)[t] = make_float4(e0, e1, e2, e3);
    out[2 + 4 * t + 0] = e0;
    out[2 + 4 * t + 1] = e1;
    out[2 + 4 * t + 2] = e2;
    out[2 + 4 * t + 3] = e3;
}

__global__ void pooled_kernel(const float* __restrict__ hf,
                              const float* __restrict__ wts,
                              float* __restrict__ pooled)
{
    const int d = threadIdx.x;
    const int n0 = blockIdx.x * 256;
    float acc = 0.f;
#pragma unroll 4
    for (int i = 0; i < 256; i++)
        acc += wts[n0 + i] * hf[(size_t)(n0 + i) * DMQ + d];
    atomicAdd(&pooled[d], acc);
}

__global__ void classifier_kernel(const float* __restrict__ pooled,
                                  const float* __restrict__ cw,
                                  const float* __restrict__ cb,
                                  float* __restrict__ out)
{
    const int lane = threadIdx.x;
    float s0 = 0.f, s1 = 0.f;
    for (int d = lane; d < DMQ; d += 32) {
        const float p = pooled[d];
        s0 += p * cw[d];
        s1 += p * cw[DMQ + d];
    }
#pragma unroll
    for (int off = 16; off; off >>= 1) {
        s0 += __shfl_xor_sync(0xffffffffu, s0, off);
        s1 += __shfl_xor_sync(0xffffffffu, s1, off);
    }
    if (lane == 0) {
        const float l0 = s0 + cb[0], l1 = s1 + cb[1];
        out[0] = 1.f / (1.f + expf(-l0));
        out[1] = 1.f / (1.f + expf(-l1));
        const float m = fmaxf(l0, l1);
        const float e0 = expf(l0 - m), e1 = expf(l1 - m);
        const float inv = 1.f / (e0 + e1);
        out[2 + NTOK] = e0 * inv;
        out[3 + NTOK] = e1 * inv;
        out[4 + NTOK] = (l1 > l0) ? 1.f : 0.f;
    }
}

// ---------------- orchestration ---------------------------------------------
static const int SMEM_N128_S4 = 4 * (128 + 128) * RSB;  // 81920
static const int SMEM_N128_S8 = 8 * (128 + 128) * RSB;  // 163840
static const int SMEM_N64_S4  = 4 * (128 + 64) * RSB;   // 61440
static const int SMEM_N64_S8  = 8 * (128 + 64) * RSB;   // 122880

extern "C" void kernel_launch(void* const* d_in, const int* in_sizes, int n_in,
                              void* d_out, int out_size)
{
    const float* x     = (const float*)d_in[0];
    const float* fc1_w = (const float*)d_in[1];
    const float* fc1_b = (const float*)d_in[2];
    const float* ln_w  = (const float*)d_in[3];
    const float* ln_b  = (const float*)d_in[4];
    const float* ipw   = (const float*)d_in[5];
    const float* cw    = (const float*)d_in[6];
    const float* cb    = (const float*)d_in[7];
    const float* xpw   = (const float*)d_in[8];
    const float* dtw   = (const float*)d_in[9];
    const float* dtb   = (const float*)d_in[10];
    const float* Alog  = (const float*)d_in[11];
    const float* Dv    = (const float*)d_in[12];
    const float* opw   = (const float*)d_in[13];
    const float* nw    = (const float*)d_in[14];
    const float* nb    = (const float*)d_in[15];
    const float* aw1   = (const float*)d_in[16];
    const float* ab1   = (const float*)d_in[17];
    const float* aw2   = (const float*)d_in[18];
    const float* ab2   = (const float*)d_in[19];
    const float* cwc   = (const float*)d_in[20];
    const float* cbc   = (const float*)d_in[21];
    float* out = (float*)d_out;

    float *p_h, *p_ln, *p_dbc, *p_dbcp;
    float *p_Aend, *p_Hend, *p_Hstart, *p_k, *p_asc, *p_wts, *p_pooled;
    bf16 *p_x16, *p_ln16, *p_xz16, *p_xs16, *p_dbc16, *p_delta16, *p_y16;
    bf16 *p_fc1w16, *p_ipw16, *p_xpw16, *p_dtw16, *p_opw16, *p_aw116;
    cudaGetSymbolAddress((void**)&p_h, g_h);
    cudaGetSymbolAddress((void**)&p_ln, g_ln);
    cudaGetSymbolAddress((void**)&p_dbc, g_dbc);
    cudaGetSymbolAddress((void**)&p_dbcp, g_dbcp);
    cudaGetSymbolAddress((void**)&p_Aend, g_Aend);
    cudaGetSymbolAddress((void**)&p_Hend, g_Hend);
    cudaGetSymbolAddress((void**)&p_Hstart, g_Hstart);
    cudaGetSymbolAddress((void**)&p_k, g_attnk);
    cudaGetSymbolAddress((void**)&p_asc, g_asc);
    cudaGetSymbolAddress((void**)&p_wts, g_wts);
    cudaGetSymbolAddress((void**)&p_pooled, g_pooled);
    cudaGetSymbolAddress((void**)&p_x16, g_x16);
    cudaGetSymbolAddress((void**)&p_ln16, g_ln16);
    cudaGetSymbolAddress((void**)&p_xz16, g_xz16);
    cudaGetSymbolAddress((void**)&p_xs16, g_xs16);
    cudaGetSymbolAddress((void**)&p_dbc16, g_dbc16);
    cudaGetSymbolAddress((void**)&p_delta16, g_delta16);
    cudaGetSymbolAddress((void**)&p_y16, g_y16);
    cudaGetSymbolAddress((void**)&p_fc1w16, g_fc1w16);
    cudaGetSymbolAddress((void**)&p_ipw16, g_ipw16);
    cudaGetSymbolAddress((void**)&p_xpw16, g_xpw16);
    cudaGetSymbolAddress((void**)&p_dtw16, g_dtw16);
    cudaGetSymbolAddress((void**)&p_opw16, g_opw16);
    cudaGetSymbolAddress((void**)&p_aw116, g_aw116);

    cudaFuncSetAttribute(gemm16_kernel<1, 128, 8, false, true,  false>, cudaFuncAttributeMaxDynamicSharedMemorySize, SMEM_N128_S8);
    cudaFuncSetAttribute(gemm16_kernel<3, 128, 8, false, true,  false>, cudaFuncAttributeMaxDynamicSharedMemorySize, SMEM_N128_S8);
    cudaFuncSetAttribute(gemm16_kernel<4, 64,  8, false, true,  false>, cudaFuncAttributeMaxDynamicSharedMemorySize, SMEM_N64_S8);
    cudaFuncSetAttribute(gemm16_kernel<0, 128, 4, true,  false, false>, cudaFuncAttributeMaxDynamicSharedMemorySize, SMEM_N128_S4);
    cudaFuncSetAttribute(gemm16_kernel<2, 128, 4, true,  false, false>, cudaFuncAttributeMaxDynamicSharedMemorySize, SMEM_N128_S4);
    cudaFuncSetAttribute(gemm16_kernel<0, 64,  4, false, true,  true >, cudaFuncAttributeMaxDynamicSharedMemorySize, SMEM_N64_S4);

    // converts (3 launches)
    {
        int n0 = NTOK * F0Q / 4;
        cvt3_kernel<<<(n0 + 255) / 256, 256>>>(x, p_x16, n0,
                                               (const float*)0, (bf16*)0, 0,
                                               (const float*)0, (bf16*)0, 0);
        int a = DMQ * F0Q / 4, b = NLQ * 2 * DIQ * DMQ / 4, c = NLQ * DMQ * DIQ / 4;
        cvt3_kernel<<<(a + b + c + 255) / 256, 256>>>(fc1_w, p_fc1w16, a,
                                                      ipw, p_ipw16, b,
                                                      opw, p_opw16, c);
        int d = NLQ * 64 * DIQ / 4, e = NLQ * DIQ * DTRQ / 4, f = 128 * DMQ / 4;
        cvt3_kernel<<<(d + e + f + 255) / 256, 256>>>(xpw, p_xpw16, d,
                                                      dtw, p_dtw16, e,
                                                      aw1, p_aw116, f);
    }

    // h = relu(x @ fc1_w^T + fc1_b)   (8-stage, 512 threads)
    gemm16_kernel<1, 128, 8, false, true, false><<<dim3(DMQ / 128, NTOK / 128), 512, SMEM_N128_S8>>>(
        p_x16, F0Q, p_fc1w16, F0Q, p_h, DMQ, (bf16*)0, fc1_b, 0, F0Q);

    for (int l = 0; l < NLQ; l++) {
        layernorm_kernel<false><<<NTOK, 128>>>(p_h, ln_w + l * DMQ, ln_b + l * DMQ,
                                               (float*)0, p_ln16);

        // xz = h_ln @ ipw^T  (bf16-only; 4-stage, 256 threads)
        gemm16_kernel<0, 128, 4, true, false, false><<<dim3(2 * DIQ / 128, NTOK / 128), 256, SMEM_N128_S4>>>(
            p_ln16, DMQ, p_ipw16 + (size_t)l * 2 * DIQ * DMQ, DMQ, (float*)0, 2 * DIQ,
            p_xz16, (const float*)0, 0, DMQ);

        // xs = silu(conv(xin) + cb)  (bf16-only)
        conv_silu_kernel<<<NTOK * DIQ / 4 / 256, 256>>>(
            p_xz16, cw + l * DIQ * DCQ, cb + l * DIQ, p_xs16);

        // dbc = xs @ xpw^T via split-K x8
        gemm16_kernel<0, 64, 4, false, true, true><<<dim3(1, NTOK / 128, KSPLIT), 256, SMEM_N64_S4>>>(
            p_xs16, DIQ, p_xpw16 + (size_t)l * 64 * DIQ, DIQ, p_dbcp, 64,
            (bf16*)0, (const float*)0, NTOK * 64, DIQ / KSPLIT);
        dbc_reduce_kernel<<<NTOK * 64 / 4 / 256, 256>>>(p_dbcp, p_dbc, p_dbc16);

        // delta = softplus(dt @ dtw^T + dtb)  (bf16-only output)
        gemm16_kernel<2, 128, 4, true, false, false><<<dim3(DIQ / 128, NTOK / 128), 256, SMEM_N128_S4>>>(
            p_dbc16, 64, p_dtw16 + (size_t)l * DIQ * DTRQ, DTRQ, (float*)0, DIQ,
            p_delta16, dtb + l * DIQ, 0, DTRQ);

        // chunked selective scan (bf16, vectorized loads)
        scan_chunk_kernel<false><<<dim3(DIQ / DGR, 64), 512>>>(
            p_delta16, p_xs16, p_dbc, (const bf16*)0,
            Alog + (size_t)l * DIQ * DSQ, (const float*)0, (const float*)0,
            p_Aend, p_Hend, (bf16*)0);
        scan_combine_kernel<<<DIQ * DSQ / 256, 256>>>(p_Aend, p_Hend, p_Hstart);
        scan_chunk_kernel<true><<<dim3(DIQ / DGR, 64), 512>>>(
            p_delta16, p_xs16, p_dbc, p_xz16,
            Alog + (size_t)l * DIQ * DSQ, Dv + l * DIQ, p_Hstart,
            (float*)0, (float*)0, p_y16);

        // h = h + y @ opw^T   (8-stage, 512 threads)
        gemm16_kernel<3, 128, 8, false, true, false><<<dim3(DMQ / 128, NTOK / 128), 512, SMEM_N128_S8>>>(
            p_y16, DIQ, p_opw16 + (size_t)l * DMQ * DIQ, DIQ, p_h, DMQ,
            (bf16*)0, p_h, DMQ, DIQ);
    }

    layernorm_kernel<true><<<NTOK, 128>>>(p_h, nw, nb, p_ln, p_ln16);

    // k = tanh(h_f @ aw1^T + ab1)   (8-stage, 512 threads)
    gemm16_kernel<4, 64, 8, false, true, false><<<dim3(2, NTOK / 128), 512, SMEM_N64_S8>>>(
        p_ln16, DMQ, p_aw116, DMQ, p_k, 128, (bf16*)0, ab1, 0, DMQ);

    asc_kernel<<<NTOK / 32, 1024>>>(p_k, aw2, ab2, p_asc);
    softmax_kernel<<<1, 1024>>>(p_asc, p_wts, out);

    cudaMemsetAsync(p_pooled, 0, DMQ * sizeof(float));
    pooled_kernel<<<16, 512>>>(p_ln, p_wts, p_pooled);
    classifier_kernel<<<1, 32>>>(p_pooled, cwc, cbc, out);
}